// round 3
// baseline (speedup 1.0000x reference)
#include <cuda_runtime.h>

// Scratch (allocation-free): projected NDC xy per vertex, and coverage bitmask.
#define MAX_BV 65536
__device__ float2 g_proj[MAX_BV];
__device__ unsigned int g_mask[65536];   // supports B*S*S <= 2M pixels

__global__ void zero_mask_kernel(int nwords) {
    int i = blockIdx.x * blockDim.x + threadIdx.x;
    if (i < nwords) g_mask[i] = 0u;
}

// Projection — byte-identical arithmetic to the reference.
__global__ void project_kernel(const float* __restrict__ verts,
                               const float* __restrict__ cams,
                               int B, int V) {
    int i = blockIdx.x * blockDim.x + threadIdx.x;
    if (i >= B * V) return;
    int b = i / V;
    float f  = cams[b * 3 + 0];
    float cx = cams[b * 3 + 1];
    float cy = cams[b * 3 + 2];
    float image_size = cams[1] * 2.0f;   // cams[0,1] * 2 per reference
    float x = verts[i * 3 + 0];
    float y = verts[i * 3 + 1];
    float z = verts[i * 3 + 2];
    float px = f * x / z + cx;
    float py = f * y / z + cy;
    g_proj[i] = make_float2(px / image_size * 2.0f - 1.0f,
                            py / image_size * 2.0f - 1.0f);
}

// Exact per-pixel test — byte-identical expressions to the R1 passing kernel.
__device__ __forceinline__ bool inside_test(
    float px, float py,
    float v0x, float v0y, float v1x, float v1y, float v2x, float v2y,
    float dy0, float dx0, float dy1, float dx1, float dy2, float dx2)
{
    float w0 = (px - v1x) * dy0 - (py - v1y) * dx0;
    float w1 = (px - v2x) * dy1 - (py - v2y) * dx1;
    float w2 = (px - v0x) * dy2 - (py - v0y) * dx2;
    bool pos = (w0 >= 0.0f) & (w1 >= 0.0f) & (w2 >= 0.0f);
    bool neg = (w0 <= 0.0f) & (w1 <= 0.0f) & (w2 <= 0.0f);
    return pos | neg;
}

// One CTA per (batch, face); thread = one scanline row of the bbox.
// t_e := (-sign(area)) * w_e  is >= 0 on the interior (w0+w1+w2 = -area for
// this edge-function convention). Per row: conservative interval [jlo,jhi]
// (superset of accepted pixels), certain-interior [jloI,jhiI] (filled without
// testing), exact reference tests only in the boundary bands.
__global__ void __launch_bounds__(128)
raster_kernel(const int* __restrict__ faces, int B, int V, int F, int S) {
    int t = blockIdx.x;
    int b = t / F;
    const int* fv = faces + t * 3;
    float2 v0 = g_proj[b * V + fv[0]];
    float2 v1 = g_proj[b * V + fv[1]];
    float2 v2 = g_proj[b * V + fv[2]];

    // Validity cull, identical to reference
    float area = (v1.x - v0.x) * (v2.y - v0.y) - (v1.y - v0.y) * (v2.x - v0.x);
    if (!(fabsf(area) > 1e-12f)) return;
    float ss = area > 0.0f ? -1.0f : 1.0f;     // interior: ss*w >= 0

    float minx = fminf(v0.x, fminf(v1.x, v2.x));
    float maxx = fmaxf(v0.x, fmaxf(v1.x, v2.x));
    float miny = fminf(v0.y, fminf(v1.y, v2.y));
    float maxy = fmaxf(v0.y, fmaxf(v1.y, v2.y));

    float half = 0.5f * (float)S;
    int x0 = max(0,     (int)floorf((minx + 1.0f) * half - 0.5f) - 1);
    int x1 = min(S - 1, (int)ceilf ((maxx + 1.0f) * half - 0.5f) + 1);
    int y0 = max(0,     (int)floorf((miny + 1.0f) * half - 0.5f) - 1);
    int y1 = min(S - 1, (int)ceilf ((maxy + 1.0f) * half - 0.5f) + 1);
    if (x1 < x0 || y1 < y0) return;

    float invS = 1.0f / (float)S;               // S power of 2 -> exact
    float px0  = (2.0f * (float)x0 + 1.0f) * invS - 1.0f;
    float pixw = 2.0f * invS;

    // Edge params matching reference w0/w1/w2 definitions
    float ax[3], ay[3], dX[3], dY[3], G[3], iG[3];
    ax[0] = v1.x; ay[0] = v1.y; dX[0] = v2.x - v1.x; dY[0] = v2.y - v1.y;
    ax[1] = v2.x; ay[1] = v2.y; dX[1] = v0.x - v2.x; dY[1] = v0.y - v2.y;
    ax[2] = v0.x; ay[2] = v0.y; dX[2] = v1.x - v0.x; dY[2] = v1.y - v0.y;
#pragma unroll
    for (int e = 0; e < 3; e++) {
        G[e]  = ss * dY[e] * pixw;              // d(t)/d(pixel x index)
        iG[e] = 1.0f / G[e];
    }

    const float EPS  = 2e-5f;      // conservative include slack
    const float EPS2 = 2e-5f;      // certainty slack
    const float GMIN = 1e-4f;      // |G| below this: no division, no certainty
    const float RV   = 512.0f * GMIN + 1e-6f;   // max |G*j| for small-G edges
    int mwords = S >> 5;

    for (int iy = y0 + threadIdx.x; iy <= y1; iy += 128) {
        float py = (2.0f * (float)iy + 1.0f) * invS - 1.0f;

        float loF = -1e9f, hiF = 1e9f;          // conservative interval (j units)
        float loC = -1e9f, hiC = 1e9f;          // certain-interior interval
        bool reject = false;
#pragma unroll
        for (int e = 0; e < 3; e++) {
            float wb = ss * ((px0 - ax[e]) * dY[e] - (py - ay[e]) * dX[e]);
            float g = G[e];
            if (fabsf(g) > GMIN) {
                float tI = (-EPS  - wb) * iG[e];
                float tC = ( EPS2 - wb) * iG[e];
                if (g > 0.0f) { loF = fmaxf(loF, tI); loC = fmaxf(loC, tC); }
                else          { hiF = fminf(hiF, tI); hiC = fminf(hiC, tC); }
            } else {
                if (wb < -(EPS + RV))  reject = true;  // t < -EPS on whole row
                if (wb <  (EPS2 + RV)) loC = 1e9f;     // no certain region
            }
        }
        if (reject) continue;

        loF = fmaxf(fminf(loF, 1e4f), -1e4f);
        hiF = fmaxf(fminf(hiF, 1e4f), -1e4f);
        loC = fmaxf(fminf(loC, 1e4f), -1e4f);
        hiC = fmaxf(fminf(hiC, 1e4f), -1e4f);

        int jlo = max(0,       (int)floorf(loF) - 1);
        int jhi = min(x1 - x0, (int)ceilf (hiF) + 1);
        if (jhi < jlo) continue;
        int jloI = max((int)ceilf (loC) + 1, jlo);
        int jhiI = min((int)floorf(hiC) - 1, jhi);

        int ixlo  = x0 + jlo,  ixhi  = x0 + jhi;
        int ixloI = x0 + jloI, ixhiI = x0 + jhiI;   // may be empty (loI > hiI)

        unsigned int* mrow = g_mask + (b * S + iy) * mwords;
        for (int w = (ixlo >> 5); w <= (ixhi >> 5); w++) {
            int wbase = w << 5;
            int lo_w = max(ixlo, wbase);
            int hi_w = min(ixhi, wbase + 31);
            unsigned int m = 0u;

            // certain-interior fill bits (no test needed)
            int cl = max(ixloI, lo_w), ch = min(ixhiI, hi_w);
            if (ch >= cl)
                m = (0xFFFFFFFFu >> (31 - (ch - cl))) << (cl - wbase);

            // exact-test left boundary band
            int bl = min(hi_w, ixloI - 1);
            for (int ix = lo_w; ix <= bl; ix++) {
                float px = (2.0f * (float)ix + 1.0f) * invS - 1.0f;
                if (inside_test(px, py, v0.x, v0.y, v1.x, v1.y, v2.x, v2.y,
                                dY[0], dX[0], dY[1], dX[1], dY[2], dX[2]))
                    m |= 1u << (ix - wbase);
            }
            // exact-test right boundary band (no overlap with left band)
            int ar = max(max(lo_w, ixhiI + 1), bl + 1);
            for (int ix = ar; ix <= hi_w; ix++) {
                float px = (2.0f * (float)ix + 1.0f) * invS - 1.0f;
                if (inside_test(px, py, v0.x, v0.y, v1.x, v1.y, v2.x, v2.y,
                                dY[0], dX[0], dY[1], dX[1], dY[2], dX[2]))
                    m |= 1u << (ix - wbase);
            }
            if (m) atomicOr(&mrow[w], m);
        }
    }
}

// Bitmask -> float output (writes every pixel; out is poisoned before timing).
__global__ void expand_kernel(float* __restrict__ out, int n) {
    int i = blockIdx.x * blockDim.x + threadIdx.x;
    if (i < n)
        out[i] = ((g_mask[i >> 5] >> (i & 31)) & 1u) ? 1.0f : 0.0f;
}

extern "C" void kernel_launch(void* const* d_in, const int* in_sizes, int n_in,
                              void* d_out, int out_size) {
    const float* verts = (const float*)d_in[0];   // [B,V,3] fp32
    const int*   faces = (const int*)d_in[1];     // [B,F,3] int32
    const float* cams  = (const float*)d_in[2];   // [B,3]   fp32

    int B = in_sizes[2] / 3;
    int V = in_sizes[0] / (3 * B);
    int F = in_sizes[1] / (3 * B);
    int S = 256;
    {   // derive S from out_size (S*S = out_size/B, S a power of two)
        int ss = out_size / B;
        int s = 1;
        while (s * s < ss) s <<= 1;
        if (s * s == ss) S = s;
    }

    float* out = (float*)d_out;
    int nwords = out_size / 32;

    zero_mask_kernel<<<(nwords + 255) / 256, 256>>>(nwords);
    project_kernel<<<(B * V + 127) / 128, 128>>>(verts, cams, B, V);
    raster_kernel<<<B * F, 128>>>(faces, B, V, F, S);
    expand_kernel<<<(out_size + 255) / 256, 256>>>(out, out_size);
}

// round 4
// speedup vs baseline: 1.2899x; 1.2899x over previous
#include <cuda_runtime.h>

// ---- static scratch (allocation-free) ----
#define MAX_BV    65536            // B*V vertices
#define MAX_BF    32768            // B*F faces
#define TS        16               // tile size in pixels
#define MAXTILES  1024             // B * (S/TS)^2  (2*256 = 512 used)
#define CAP       8192             // per-tile list capacity (>= F)

__device__ float2 g_proj[MAX_BV];
__device__ float4 g_triA[MAX_BF];  // (v1x, v1y, dY0, dX0)
__device__ float4 g_triB[MAX_BF];  // (v2x, v2y, dY1, dX1)
__device__ float4 g_triC[MAX_BF];  // (v0x, v0y, dY2, dX2)
__device__ int    g_cnt[MAXTILES];
__device__ int    g_bins[MAXTILES * CAP];   // 32 MB

__global__ void zero_cnt_kernel() {
    int i = blockIdx.x * blockDim.x + threadIdx.x;
    if (i < MAXTILES) g_cnt[i] = 0;
}

// Projection — byte-identical arithmetic to the reference.
__global__ void project_kernel(const float* __restrict__ verts,
                               const float* __restrict__ cams,
                               int B, int V) {
    int i = blockIdx.x * blockDim.x + threadIdx.x;
    if (i >= B * V) return;
    int b = i / V;
    float f  = cams[b * 3 + 0];
    float cx = cams[b * 3 + 1];
    float cy = cams[b * 3 + 2];
    float image_size = cams[1] * 2.0f;   // cams[0,1] * 2 per reference
    float x = verts[i * 3 + 0];
    float y = verts[i * 3 + 1];
    float z = verts[i * 3 + 2];
    float px = f * x / z + cx;
    float py = f * y / z + cy;
    g_proj[i] = make_float2(px / image_size * 2.0f - 1.0f,
                            py / image_size * 2.0f - 1.0f);
}

// Bin faces into per-(batch,tile) lists. Smem-aggregated counts -> one global
// reservation atomicAdd per (CTA,tile) -> scatter entries. Also emits the
// per-face edge coefficients used by the raster loop.
__global__ void __launch_bounds__(256)
bin_kernel(const int* __restrict__ faces, int B, int V, int F, int S, int NT) {
    __shared__ int s_cnt[MAXTILES];
    __shared__ int s_base[MAXTILES];
    for (int i = threadIdx.x; i < MAXTILES; i += 256) s_cnt[i] = 0;
    __syncthreads();

    int t = blockIdx.x * 256 + threadIdx.x;
    bool valid = false;
    int tx0 = 0, tx1 = -1, ty0 = 0, ty1 = -1, tbase = 0;
    if (t < B * F) {
        int b = t / F;
        const int* fv = faces + t * 3;
        float2 v0 = g_proj[b * V + fv[0]];
        float2 v1 = g_proj[b * V + fv[1]];
        float2 v2 = g_proj[b * V + fv[2]];
        float area = (v1.x - v0.x) * (v2.y - v0.y)
                   - (v1.y - v0.y) * (v2.x - v0.x);
        if (fabsf(area) > 1e-12f) {
            valid = true;
            g_triA[t] = make_float4(v1.x, v1.y, v2.y - v1.y, v2.x - v1.x);
            g_triB[t] = make_float4(v2.x, v2.y, v0.y - v2.y, v0.x - v2.x);
            g_triC[t] = make_float4(v0.x, v0.y, v1.y - v0.y, v1.x - v0.x);

            float minx = fminf(v0.x, fminf(v1.x, v2.x));
            float maxx = fmaxf(v0.x, fmaxf(v1.x, v2.x));
            float miny = fminf(v0.y, fminf(v1.y, v2.y));
            float maxy = fmaxf(v0.y, fmaxf(v1.y, v2.y));
            float half = 0.5f * (float)S;
            int x0 = max(0,     (int)floorf((minx + 1.0f) * half - 0.5f) - 1);
            int x1 = min(S - 1, (int)ceilf ((maxx + 1.0f) * half - 0.5f) + 1);
            int y0 = max(0,     (int)floorf((miny + 1.0f) * half - 0.5f) - 1);
            int y1 = min(S - 1, (int)ceilf ((maxy + 1.0f) * half - 0.5f) + 1);
            if (x1 < x0 || y1 < y0) {
                valid = false;
            } else {
                tx0 = x0 / TS; tx1 = x1 / TS;
                ty0 = y0 / TS; ty1 = y1 / TS;
                tbase = b * NT * NT;
                for (int ty = ty0; ty <= ty1; ty++)
                    for (int tx = tx0; tx <= tx1; tx++)
                        atomicAdd(&s_cnt[tbase + ty * NT + tx], 1);
            }
        }
    }
    __syncthreads();
    for (int i = threadIdx.x; i < MAXTILES; i += 256) {
        int c = s_cnt[i];
        s_base[i] = c ? atomicAdd(&g_cnt[i], c) : 0;
        s_cnt[i] = 0;
    }
    __syncthreads();
    if (valid) {
        for (int ty = ty0; ty <= ty1; ty++)
            for (int tx = tx0; tx <= tx1; tx++) {
                int tile = tbase + ty * NT + tx;
                int pos = s_base[tile] + atomicAdd(&s_cnt[tile], 1);
                g_bins[tile * CAP + pos] = t;
            }
    }
}

// One CTA per (batch, 16x16 tile); one thread per pixel. Loop over the tile's
// triangle list; per-warp early exit once all 32 pixels are covered.
// Edge test is byte-identical to the R1-passing kernel.
__global__ void __launch_bounds__(256)
raster_kernel(float* __restrict__ out, int F, int S, int NT) {
    int tile = blockIdx.x;
    int b   = tile / (NT * NT);
    int rem = tile - b * (NT * NT);
    int tyT = rem / NT, txT = rem - tyT * NT;
    int ix = txT * TS + (threadIdx.x & (TS - 1));
    int iy = tyT * TS + (threadIdx.x / TS);

    float invS = 1.0f / (float)S;
    float px = (2.0f * (float)ix + 1.0f) * invS - 1.0f;
    float py = (2.0f * (float)iy + 1.0f) * invS - 1.0f;

    int n = g_cnt[tile];
    const int* list = g_bins + tile * CAP;

    bool cov = false;
    for (int k = 0; k < n; k++) {
        int f = list[k];                       // uniform across CTA
        float4 A = g_triA[f];
        float4 Bq = g_triB[f];
        float4 C = g_triC[f];
        float w0 = (px - A.x)  * A.z  - (py - A.y)  * A.w;
        float w1 = (px - Bq.x) * Bq.z - (py - Bq.y) * Bq.w;
        float w2 = (px - C.x)  * C.z  - (py - C.y)  * C.w;
        bool pos = (w0 >= 0.0f) & (w1 >= 0.0f) & (w2 >= 0.0f);
        bool neg = (w0 <= 0.0f) & (w1 <= 0.0f) & (w2 <= 0.0f);
        cov |= (pos | neg);
        if (__all_sync(0xFFFFFFFFu, cov)) break;
    }
    out[(b * S + iy) * S + ix] = cov ? 1.0f : 0.0f;
}

extern "C" void kernel_launch(void* const* d_in, const int* in_sizes, int n_in,
                              void* d_out, int out_size) {
    const float* verts = (const float*)d_in[0];   // [B,V,3] fp32
    const int*   faces = (const int*)d_in[1];     // [B,F,3] int32
    const float* cams  = (const float*)d_in[2];   // [B,3]   fp32

    int B = in_sizes[2] / 3;
    int V = in_sizes[0] / (3 * B);
    int F = in_sizes[1] / (3 * B);
    int S = 256;
    {   // derive S from out_size (S*S = out_size/B, S a power of two)
        int ss = out_size / B;
        int s = 1;
        while (s * s < ss) s <<= 1;
        if (s * s == ss) S = s;
    }
    int NT = S / TS;

    float* out = (float*)d_out;

    zero_cnt_kernel<<<(MAXTILES + 255) / 256, 256>>>();
    project_kernel<<<(B * V + 127) / 128, 128>>>(verts, cams, B, V);
    bin_kernel<<<(B * F + 255) / 256, 256>>>(faces, B, V, F, S, NT);
    raster_kernel<<<B * NT * NT, 256>>>(out, F, S, NT);
}

// round 5
// speedup vs baseline: 3.4026x; 2.6378x over previous
#include <cuda_runtime.h>

// ---- static scratch (allocation-free) ----
#define MAX_BV    65536            // B*V vertices
#define MAX_BF    32768            // B*F faces
#define TS        16               // tile size in pixels
#define MAXTILES  1024             // B * (S/TS)^2  (2*256 = 512 used)
#define CAP       8192             // per-tile list capacity (>= F)
#define BATCH     32               // triangles staged per smem batch

__device__ float2 g_proj[MAX_BV];
__device__ float4 g_triA[MAX_BF];  // (v1x, v1y, dY0, dX0)
__device__ float4 g_triB[MAX_BF];  // (v2x, v2y, dY1, dX1)
__device__ float4 g_triC[MAX_BF];  // (v0x, v0y, dY2, dX2)
__device__ int    g_cnt[MAXTILES];
__device__ int    g_bins[MAXTILES * CAP];

__global__ void zero_cnt_kernel() {
    int i = blockIdx.x * blockDim.x + threadIdx.x;
    if (i < MAXTILES) g_cnt[i] = 0;
}

// Projection — byte-identical arithmetic to the reference.
__global__ void project_kernel(const float* __restrict__ verts,
                               const float* __restrict__ cams,
                               int B, int V) {
    int i = blockIdx.x * blockDim.x + threadIdx.x;
    if (i >= B * V) return;
    int b = i / V;
    float f  = cams[b * 3 + 0];
    float cx = cams[b * 3 + 1];
    float cy = cams[b * 3 + 2];
    float image_size = cams[1] * 2.0f;   // cams[0,1] * 2 per reference
    float x = verts[i * 3 + 0];
    float y = verts[i * 3 + 1];
    float z = verts[i * 3 + 2];
    float px = f * x / z + cx;
    float py = f * y / z + cy;
    g_proj[i] = make_float2(px / image_size * 2.0f - 1.0f,
                            py / image_size * 2.0f - 1.0f);
}

// Bin faces into per-(batch,tile) lists; emit per-face edge coefficients.
__global__ void __launch_bounds__(256)
bin_kernel(const int* __restrict__ faces, int B, int V, int F, int S, int NT) {
    __shared__ int s_cnt[MAXTILES];
    __shared__ int s_base[MAXTILES];
    for (int i = threadIdx.x; i < MAXTILES; i += 256) s_cnt[i] = 0;
    __syncthreads();

    int t = blockIdx.x * 256 + threadIdx.x;
    bool valid = false;
    int tx0 = 0, tx1 = -1, ty0 = 0, ty1 = -1, tbase = 0;
    if (t < B * F) {
        int b = t / F;
        const int* fv = faces + t * 3;
        float2 v0 = g_proj[b * V + fv[0]];
        float2 v1 = g_proj[b * V + fv[1]];
        float2 v2 = g_proj[b * V + fv[2]];
        float area = (v1.x - v0.x) * (v2.y - v0.y)
                   - (v1.y - v0.y) * (v2.x - v0.x);
        if (fabsf(area) > 1e-12f) {
            valid = true;
            g_triA[t] = make_float4(v1.x, v1.y, v2.y - v1.y, v2.x - v1.x);
            g_triB[t] = make_float4(v2.x, v2.y, v0.y - v2.y, v0.x - v2.x);
            g_triC[t] = make_float4(v0.x, v0.y, v1.y - v0.y, v1.x - v0.x);

            float minx = fminf(v0.x, fminf(v1.x, v2.x));
            float maxx = fmaxf(v0.x, fmaxf(v1.x, v2.x));
            float miny = fminf(v0.y, fminf(v1.y, v2.y));
            float maxy = fmaxf(v0.y, fmaxf(v1.y, v2.y));
            float half = 0.5f * (float)S;
            int x0 = max(0,     (int)floorf((minx + 1.0f) * half - 0.5f) - 1);
            int x1 = min(S - 1, (int)ceilf ((maxx + 1.0f) * half - 0.5f) + 1);
            int y0 = max(0,     (int)floorf((miny + 1.0f) * half - 0.5f) - 1);
            int y1 = min(S - 1, (int)ceilf ((maxy + 1.0f) * half - 0.5f) + 1);
            if (x1 < x0 || y1 < y0) {
                valid = false;
            } else {
                tx0 = x0 / TS; tx1 = x1 / TS;
                ty0 = y0 / TS; ty1 = y1 / TS;
                tbase = b * NT * NT;
                for (int ty = ty0; ty <= ty1; ty++)
                    for (int tx = tx0; tx <= tx1; tx++)
                        atomicAdd(&s_cnt[tbase + ty * NT + tx], 1);
            }
        }
    }
    __syncthreads();
    for (int i = threadIdx.x; i < MAXTILES; i += 256) {
        int c = s_cnt[i];
        s_base[i] = c ? atomicAdd(&g_cnt[i], c) : 0;
        s_cnt[i] = 0;
    }
    __syncthreads();
    if (valid) {
        for (int ty = ty0; ty <= ty1; ty++)
            for (int tx = tx0; tx <= tx1; tx++) {
                int tile = tbase + ty * NT + tx;
                int pos = s_base[tile] + atomicAdd(&s_cnt[tile], 1);
                g_bins[tile * CAP + pos] = t;
            }
    }
}

// One CTA per (batch, 16x16 tile); one thread per pixel. Triangle data staged
// through SMEM in batches; CTA-wide early exit per batch, warp-level early
// break within a batch. Edge test byte-identical to the R1-passing kernel.
__global__ void __launch_bounds__(256)
raster_kernel(float* __restrict__ out, int S, int NT) {
    __shared__ float4 sA[BATCH], sB[BATCH], sC[BATCH];

    int tile = blockIdx.x;
    int b   = tile / (NT * NT);
    int rem = tile - b * (NT * NT);
    int tyT = rem / NT, txT = rem - tyT * NT;
    int tid = threadIdx.x;
    int ix = txT * TS + (tid & (TS - 1));
    int iy = tyT * TS + (tid >> 4);

    float invS = 1.0f / (float)S;
    float px = (2.0f * (float)ix + 1.0f) * invS - 1.0f;
    float py = (2.0f * (float)iy + 1.0f) * invS - 1.0f;

    int n = g_cnt[tile];
    const int* list = g_bins + tile * CAP;

    bool cov = false;
    for (int k0 = 0; k0 < n; k0 += BATCH) {
        int cnt = min(BATCH, n - k0);
        // stage batch: 3*cnt float4 gathers done once per CTA
        if (tid < cnt) {
            int f = list[k0 + tid];
            sA[tid] = g_triA[f];
        } else if (tid < 2 * cnt) {
            int f = list[k0 + tid - cnt];
            sB[tid - cnt] = g_triB[f];
        } else if (tid < 3 * cnt) {
            int f = list[k0 + tid - 2 * cnt];
            sC[tid - 2 * cnt] = g_triC[f];
        }
        __syncthreads();

        if (!__all_sync(0xFFFFFFFFu, cov)) {
            #pragma unroll 4
            for (int k = 0; k < cnt; k++) {
                float4 A  = sA[k];
                float4 Bq = sB[k];
                float4 C  = sC[k];
                float w0 = (px - A.x)  * A.z  - (py - A.y)  * A.w;
                float w1 = (px - Bq.x) * Bq.z - (py - Bq.y) * Bq.w;
                float w2 = (px - C.x)  * C.z  - (py - C.y)  * C.w;
                bool pos = (w0 >= 0.0f) & (w1 >= 0.0f) & (w2 >= 0.0f);
                bool neg = (w0 <= 0.0f) & (w1 <= 0.0f) & (w2 <= 0.0f);
                cov |= (pos | neg);
            }
        }
        // doubles as the barrier protecting smem reuse
        if (__syncthreads_and((int)cov)) break;
    }
    out[(b * S + iy) * S + ix] = cov ? 1.0f : 0.0f;
}

extern "C" void kernel_launch(void* const* d_in, const int* in_sizes, int n_in,
                              void* d_out, int out_size) {
    const float* verts = (const float*)d_in[0];   // [B,V,3] fp32
    const int*   faces = (const int*)d_in[1];     // [B,F,3] int32
    const float* cams  = (const float*)d_in[2];   // [B,3]   fp32

    int B = in_sizes[2] / 3;
    int V = in_sizes[0] / (3 * B);
    int F = in_sizes[1] / (3 * B);
    int S = 256;
    {   // derive S from out_size (S*S = out_size/B, S a power of two)
        int ss = out_size / B;
        int s = 1;
        while (s * s < ss) s <<= 1;
        if (s * s == ss) S = s;
    }
    int NT = S / TS;

    float* out = (float*)d_out;

    zero_cnt_kernel<<<(MAXTILES + 255) / 256, 256>>>();
    project_kernel<<<(B * V + 127) / 128, 128>>>(verts, cams, B, V);
    bin_kernel<<<(B * F + 255) / 256, 256>>>(faces, B, V, F, S, NT);
    raster_kernel<<<B * NT * NT, 256>>>(out, S, NT);
}

// round 6
// speedup vs baseline: 3.8524x; 1.1322x over previous
#include <cuda_runtime.h>

// ---- static scratch (allocation-free) ----
#define MAX_BV    65536            // B*V vertices
#define MAX_BF    32768            // B*F faces
#define TS        16               // tile size in pixels
#define MAXTILES  1024             // B * (S/TS)^2  (2*256 = 512 used)
#define CAP       8192             // per-tile list capacity (>= F)
#define BATCH     32               // triangles staged per smem batch

__device__ float2 g_proj[MAX_BV];
__device__ float4 g_triA[MAX_BF];  // (v1x, v1y, dY0, dX0)
__device__ float4 g_triB[MAX_BF];  // (v2x, v2y, dY1, dX1)
__device__ float4 g_triC[MAX_BF];  // (v0x, v0y, dY2, dX2)
__device__ int    g_cnt[MAXTILES];
__device__ int    g_full[MAXTILES];
__device__ int    g_bins[MAXTILES * CAP];

// Fused: zero tile metadata + project vertices (reference-identical math).
__global__ void setup_kernel(const float* __restrict__ verts,
                             const float* __restrict__ cams,
                             int B, int V) {
    int i = blockIdx.x * blockDim.x + threadIdx.x;
    if (i < MAXTILES) { g_cnt[i] = 0; g_full[i] = 0; }
    if (i >= B * V) return;
    int b = i / V;
    float f  = cams[b * 3 + 0];
    float cx = cams[b * 3 + 1];
    float cy = cams[b * 3 + 2];
    float image_size = cams[1] * 2.0f;   // cams[0,1] * 2 per reference
    float x = verts[i * 3 + 0];
    float y = verts[i * 3 + 1];
    float z = verts[i * 3 + 2];
    float px = f * x / z + cx;
    float py = f * y / z + cy;
    g_proj[i] = make_float2(px / image_size * 2.0f - 1.0f,
                            py / image_size * 2.0f - 1.0f);
}

// Bin faces into per-(batch,tile) lists with SAT cull + full-cover detection.
__global__ void __launch_bounds__(256)
bin_kernel(const int* __restrict__ faces, int B, int V, int F, int S, int NT) {
    __shared__ int s_cnt[MAXTILES];
    __shared__ int s_base[MAXTILES];
    for (int i = threadIdx.x; i < MAXTILES; i += 256) s_cnt[i] = 0;
    __syncthreads();

    int t = blockIdx.x * 256 + threadIdx.x;
    // per-thread tile span + per-tile keep mask (bbox <= 256px -> <= 17 tiles/axis)
    int tx0 = 0, tx1 = -1, ty0 = 0, ty1 = -1, tbase = 0;
    unsigned int keep[17];           // bit tx-tx0 of keep[ty-ty0]
    #pragma unroll
    for (int q = 0; q < 17; q++) keep[q] = 0u;

    float kx[3], ky[3], kc[3];
    float invS = 0.0f, span = 0.0f;

    if (t < B * F) {
        int b = t / F;
        const int* fv = faces + t * 3;
        float2 v0 = g_proj[b * V + fv[0]];
        float2 v1 = g_proj[b * V + fv[1]];
        float2 v2 = g_proj[b * V + fv[2]];
        float area = (v1.x - v0.x) * (v2.y - v0.y)
                   - (v1.y - v0.y) * (v2.x - v0.x);
        if (fabsf(area) > 1e-12f) {
            g_triA[t] = make_float4(v1.x, v1.y, v2.y - v1.y, v2.x - v1.x);
            g_triB[t] = make_float4(v2.x, v2.y, v0.y - v2.y, v0.x - v2.x);
            g_triC[t] = make_float4(v0.x, v0.y, v1.y - v0.y, v1.x - v0.x);

            float minx = fminf(v0.x, fminf(v1.x, v2.x));
            float maxx = fmaxf(v0.x, fmaxf(v1.x, v2.x));
            float miny = fminf(v0.y, fminf(v1.y, v2.y));
            float maxy = fmaxf(v0.y, fmaxf(v1.y, v2.y));
            float half = 0.5f * (float)S;
            int x0 = max(0,     (int)floorf((minx + 1.0f) * half - 0.5f) - 1);
            int x1 = min(S - 1, (int)ceilf ((maxx + 1.0f) * half - 0.5f) + 1);
            int y0 = max(0,     (int)floorf((miny + 1.0f) * half - 0.5f) - 1);
            int y1 = min(S - 1, (int)ceilf ((maxy + 1.0f) * half - 0.5f) + 1);
            if (x1 >= x0 && y1 >= y0) {
                tx0 = x0 / TS; tx1 = x1 / TS;
                ty0 = y0 / TS; ty1 = y1 / TS;
                tbase = b * NT * NT;

                // s*w_e(x,y) = kx*x + ky*y + kc,  interior: s*w >= 0
                float ss = area > 0.0f ? -1.0f : 1.0f;
                float axv[3] = {v1.x, v2.x, v0.x};
                float ayv[3] = {v1.y, v2.y, v0.y};
                float dXv[3] = {v2.x - v1.x, v0.x - v2.x, v1.x - v0.x};
                float dYv[3] = {v2.y - v1.y, v0.y - v2.y, v1.y - v0.y};
                #pragma unroll
                for (int e = 0; e < 3; e++) {
                    kx[e] = ss * dYv[e];
                    ky[e] = -ss * dXv[e];
                    kc[e] = ss * (ayv[e] * dXv[e] - axv[e] * dYv[e]);
                }
                invS = 1.0f / (float)S;
                span = 30.0f * invS;   // ndc span between corner pixel centers

                const float MARGIN = 1e-4f;
                for (int ty = ty0; ty <= ty1; ty++) {
                    float cy0 = (2.0f * (float)(ty * TS) + 1.0f) * invS - 1.0f;
                    for (int tx = tx0; tx <= tx1; tx++) {
                        float cx0 = (2.0f * (float)(tx * TS) + 1.0f) * invS - 1.0f;
                        bool full = true, cull = false;
                        #pragma unroll
                        for (int e = 0; e < 3; e++) {
                            float base = kx[e] * cx0 + ky[e] * cy0 + kc[e];
                            float dxs = kx[e] * span, dys = ky[e] * span;
                            float tmin = base + fminf(dxs, 0.0f) + fminf(dys, 0.0f);
                            float tmax = base + fmaxf(dxs, 0.0f) + fmaxf(dys, 0.0f);
                            full = full && (tmin >= MARGIN);
                            cull = cull || (tmax <= -MARGIN);
                        }
                        int tile = tbase + ty * NT + tx;
                        if (full) {
                            g_full[tile] = 1;          // raster skips this tile
                        } else if (!cull) {
                            keep[ty - ty0] |= 1u << (tx - tx0);
                            atomicAdd(&s_cnt[tile], 1);
                        }
                    }
                }
            }
        }
    }
    __syncthreads();
    for (int i = threadIdx.x; i < MAXTILES; i += 256) {
        int c = s_cnt[i];
        s_base[i] = c ? atomicAdd(&g_cnt[i], c) : 0;
        s_cnt[i] = 0;
    }
    __syncthreads();
    if (tx1 >= tx0) {
        for (int ty = ty0; ty <= ty1; ty++) {
            unsigned int row = keep[ty - ty0];
            for (int tx = tx0; tx <= tx1; tx++) {
                if (row & (1u << (tx - tx0))) {
                    int tile = tbase + ty * NT + tx;
                    int pos = s_base[tile] + atomicAdd(&s_cnt[tile], 1);
                    g_bins[tile * CAP + pos] = t;
                }
            }
        }
    }
}

// One CTA per (batch, 16x16 tile); one thread per pixel. Full tiles exit
// immediately; others scan smem-staged batches with CTA/warp early exit.
// Edge test byte-identical to the R1-passing kernel.
__global__ void __launch_bounds__(256)
raster_kernel(float* __restrict__ out, int S, int NT) {
    __shared__ float4 sA[BATCH], sB[BATCH], sC[BATCH];

    int tile = blockIdx.x;
    int b   = tile / (NT * NT);
    int rem = tile - b * (NT * NT);
    int tyT = rem / NT, txT = rem - tyT * NT;
    int tid = threadIdx.x;
    int ix = txT * TS + (tid & (TS - 1));
    int iy = tyT * TS + (tid >> 4);
    float* dst = out + (b * S + iy) * S + ix;

    if (g_full[tile]) { *dst = 1.0f; return; }

    float invS = 1.0f / (float)S;
    float px = (2.0f * (float)ix + 1.0f) * invS - 1.0f;
    float py = (2.0f * (float)iy + 1.0f) * invS - 1.0f;

    int n = g_cnt[tile];
    const int* list = g_bins + tile * CAP;

    bool cov = false;
    for (int k0 = 0; k0 < n; k0 += BATCH) {
        int cnt = min(BATCH, n - k0);
        if (tid < cnt) {
            int f = list[k0 + tid];
            sA[tid] = g_triA[f];
        } else if (tid < 2 * cnt) {
            int f = list[k0 + tid - cnt];
            sB[tid - cnt] = g_triB[f];
        } else if (tid < 3 * cnt) {
            int f = list[k0 + tid - 2 * cnt];
            sC[tid - 2 * cnt] = g_triC[f];
        }
        __syncthreads();

        if (!__all_sync(0xFFFFFFFFu, cov)) {
            #pragma unroll 4
            for (int k = 0; k < cnt; k++) {
                float4 A  = sA[k];
                float4 Bq = sB[k];
                float4 C  = sC[k];
                float w0 = (px - A.x)  * A.z  - (py - A.y)  * A.w;
                float w1 = (px - Bq.x) * Bq.z - (py - Bq.y) * Bq.w;
                float w2 = (px - C.x)  * C.z  - (py - C.y)  * C.w;
                bool pos = (w0 >= 0.0f) & (w1 >= 0.0f) & (w2 >= 0.0f);
                bool neg = (w0 <= 0.0f) & (w1 <= 0.0f) & (w2 <= 0.0f);
                cov |= (pos | neg);
            }
        }
        if (__syncthreads_and((int)cov)) break;   // also guards smem reuse
    }
    *dst = cov ? 1.0f : 0.0f;
}

extern "C" void kernel_launch(void* const* d_in, const int* in_sizes, int n_in,
                              void* d_out, int out_size) {
    const float* verts = (const float*)d_in[0];   // [B,V,3] fp32
    const int*   faces = (const int*)d_in[1];     // [B,F,3] int32
    const float* cams  = (const float*)d_in[2];   // [B,3]   fp32

    int B = in_sizes[2] / 3;
    int V = in_sizes[0] / (3 * B);
    int F = in_sizes[1] / (3 * B);
    int S = 256;
    {   // derive S from out_size (S*S = out_size/B, S a power of two)
        int ss = out_size / B;
        int s = 1;
        while (s * s < ss) s <<= 1;
        if (s * s == ss) S = s;
    }
    int NT = S / TS;

    float* out = (float*)d_out;

    int nset = max(B * V, MAXTILES);
    setup_kernel<<<(nset + 255) / 256, 256>>>(verts, cams, B, V);
    bin_kernel<<<(B * F + 255) / 256, 256>>>(faces, B, V, F, S, NT);
    raster_kernel<<<B * NT * NT, 256>>>(out, S, NT);
}

// round 7
// speedup vs baseline: 4.8420x; 1.2569x over previous
#include <cuda_runtime.h>

// ---- static scratch (allocation-free) ----
#define MAX_BV    65536            // B*V vertices
#define MAX_BF    32768            // B*F faces
#define TS        16               // tile size in pixels
#define MAXTILES  1024             // B * (S/TS)^2  (2*256 = 512 used)
#define CAP       8192             // per-tile list capacity (>= F)
#define BATCH     64               // triangles staged per smem batch
#define TPW       8                // triangles per warp in binner

__device__ float2 g_proj[MAX_BV];
__device__ float4 g_triA[MAX_BF];  // (v1x, v1y, dY0, dX0)
__device__ float4 g_triB[MAX_BF];  // (v2x, v2y, dY1, dX1)
__device__ float4 g_triC[MAX_BF];  // (v0x, v0y, dY2, dX2)
__device__ int    g_cnt[MAXTILES];
__device__ int    g_full[MAXTILES];
__device__ int    g_bins[MAXTILES * CAP];

// Fused: zero tile metadata + project vertices (reference-identical math).
__global__ void setup_kernel(const float* __restrict__ verts,
                             const float* __restrict__ cams,
                             int B, int V) {
    int i = blockIdx.x * blockDim.x + threadIdx.x;
    if (i < MAXTILES) { g_cnt[i] = 0; g_full[i] = 0; }
    if (i >= B * V) return;
    int b = i / V;
    float f  = cams[b * 3 + 0];
    float cx = cams[b * 3 + 1];
    float cy = cams[b * 3 + 2];
    float image_size = cams[1] * 2.0f;   // cams[0,1] * 2 per reference
    float x = verts[i * 3 + 0];
    float y = verts[i * 3 + 1];
    float z = verts[i * 3 + 2];
    float px = f * x / z + cx;
    float py = f * y / z + cy;
    g_proj[i] = make_float2(px / image_size * 2.0f - 1.0f,
                            py / image_size * 2.0f - 1.0f);
}

// Per-triangle setup shared by both binning phases.
struct TriBin {
    bool  ok;
    int   tx0, tx1, ty0, ty1, tbase, sx, ntiles;
    float kx[3], ky[3], kc[3];
};

__device__ __forceinline__ TriBin tri_setup(const int* __restrict__ faces,
                                            int t, int V, int F, int S, int NT) {
    TriBin r; r.ok = false;
    int b = t / F;
    const int* fv = faces + t * 3;
    float2 v0 = g_proj[b * V + fv[0]];
    float2 v1 = g_proj[b * V + fv[1]];
    float2 v2 = g_proj[b * V + fv[2]];
    float area = (v1.x - v0.x) * (v2.y - v0.y)
               - (v1.y - v0.y) * (v2.x - v0.x);
    if (!(fabsf(area) > 1e-12f)) return r;

    float minx = fminf(v0.x, fminf(v1.x, v2.x));
    float maxx = fmaxf(v0.x, fmaxf(v1.x, v2.x));
    float miny = fminf(v0.y, fminf(v1.y, v2.y));
    float maxy = fmaxf(v0.y, fmaxf(v1.y, v2.y));
    float half = 0.5f * (float)S;
    int x0 = max(0,     (int)floorf((minx + 1.0f) * half - 0.5f) - 1);
    int x1 = min(S - 1, (int)ceilf ((maxx + 1.0f) * half - 0.5f) + 1);
    int y0 = max(0,     (int)floorf((miny + 1.0f) * half - 0.5f) - 1);
    int y1 = min(S - 1, (int)ceilf ((maxy + 1.0f) * half - 0.5f) + 1);
    if (x1 < x0 || y1 < y0) return r;

    r.ok = true;
    r.tx0 = x0 / TS; r.tx1 = x1 / TS;
    r.ty0 = y0 / TS; r.ty1 = y1 / TS;
    r.tbase = b * NT * NT;
    r.sx = r.tx1 - r.tx0 + 1;
    r.ntiles = r.sx * (r.ty1 - r.ty0 + 1);

    float ss = area > 0.0f ? -1.0f : 1.0f;   // interior: ss*w >= 0
    float axv[3] = {v1.x, v2.x, v0.x};
    float ayv[3] = {v1.y, v2.y, v0.y};
    float dXv[3] = {v2.x - v1.x, v0.x - v2.x, v1.x - v0.x};
    float dYv[3] = {v2.y - v1.y, v0.y - v2.y, v1.y - v0.y};
#pragma unroll
    for (int e = 0; e < 3; e++) {
        r.kx[e] = ss * dYv[e];
        r.ky[e] = -ss * dXv[e];
        r.kc[e] = ss * (ayv[e] * dXv[e] - axv[e] * dYv[e]);
    }
    return r;
}

// Corner-based tile classification: 0 = cull, 1 = list, 2 = full-cover.
__device__ __forceinline__ int tile_class(const TriBin& r, int tx, int ty,
                                          float invS, float span) {
    float cx0 = (2.0f * (float)(tx * TS) + 1.0f) * invS - 1.0f;
    float cy0 = (2.0f * (float)(ty * TS) + 1.0f) * invS - 1.0f;
    const float MARGIN = 1e-4f;
    bool full = true, cull = false;
#pragma unroll
    for (int e = 0; e < 3; e++) {
        float base = r.kx[e] * cx0 + r.ky[e] * cy0 + r.kc[e];
        float dxs = r.kx[e] * span, dys = r.ky[e] * span;
        float tmin = base + fminf(dxs, 0.0f) + fminf(dys, 0.0f);
        float tmax = base + fmaxf(dxs, 0.0f) + fmaxf(dys, 0.0f);
        full = full && (tmin >= MARGIN);
        cull = cull || (tmax <= -MARGIN);
    }
    return full ? 2 : (cull ? 0 : 1);
}

// Warp-parallel binning: each warp takes TPW triangles (strided); the 32
// lanes split each triangle's tile span. Phase 1 counts into smem, flush
// reserves global segments, phase 2 recomputes the test and scatters.
__global__ void __launch_bounds__(256)
bin_kernel(const int* __restrict__ faces, int B, int V, int F, int S, int NT) {
    __shared__ int s_cnt[MAXTILES];
    __shared__ int s_base[MAXTILES];
    for (int i = threadIdx.x; i < MAXTILES; i += 256) s_cnt[i] = 0;
    __syncthreads();

    int BF = B * F;
    int warpsTotal = gridDim.x * 8;
    int warpId = blockIdx.x * 8 + (threadIdx.x >> 5);
    int lane = threadIdx.x & 31;
    float invS = 1.0f / (float)S;
    float span = 30.0f * invS;   // ndc span between tile corner pixel centers

    // phase 1: counts (+ coefficient emit + full flags)
    for (int k = 0; k < TPW; k++) {
        int t = warpId + k * warpsTotal;
        if (t >= BF) break;
        TriBin r = tri_setup(faces, t, V, F, S, NT);
        if (!r.ok) continue;
        if (lane == 0) {
            int b = t / F;
            const int* fv = faces + t * 3;
            float2 v0 = g_proj[b * V + fv[0]];
            float2 v1 = g_proj[b * V + fv[1]];
            float2 v2 = g_proj[b * V + fv[2]];
            g_triA[t] = make_float4(v1.x, v1.y, v2.y - v1.y, v2.x - v1.x);
            g_triB[t] = make_float4(v2.x, v2.y, v0.y - v2.y, v0.x - v2.x);
            g_triC[t] = make_float4(v0.x, v0.y, v1.y - v0.y, v1.x - v0.x);
        }
        for (int i = lane; i < r.ntiles; i += 32) {
            int tx = r.tx0 + (i % r.sx);
            int ty = r.ty0 + (i / r.sx);
            int tile = r.tbase + ty * NT + tx;
            int c = tile_class(r, tx, ty, invS, span);
            if (c == 2)      g_full[tile] = 1;
            else if (c == 1) atomicAdd(&s_cnt[tile], 1);
        }
    }
    __syncthreads();
    for (int i = threadIdx.x; i < MAXTILES; i += 256) {
        int c = s_cnt[i];
        s_base[i] = c ? atomicAdd(&g_cnt[i], c) : 0;
        s_cnt[i] = 0;
    }
    __syncthreads();
    // phase 2: scatter (recompute classification)
    for (int k = 0; k < TPW; k++) {
        int t = warpId + k * warpsTotal;
        if (t >= BF) break;
        TriBin r = tri_setup(faces, t, V, F, S, NT);
        if (!r.ok) continue;
        for (int i = lane; i < r.ntiles; i += 32) {
            int tx = r.tx0 + (i % r.sx);
            int ty = r.ty0 + (i / r.sx);
            int tile = r.tbase + ty * NT + tx;
            if (tile_class(r, tx, ty, invS, span) == 1) {
                int pos = s_base[tile] + atomicAdd(&s_cnt[tile], 1);
                g_bins[tile * CAP + pos] = t;
            }
        }
    }
}

// One CTA per (batch, 16x16 tile); one thread per pixel. Full tiles exit
// immediately; others scan smem-staged batches with CTA/warp early exit.
// Edge test byte-identical to the R1-passing kernel.
__global__ void __launch_bounds__(256)
raster_kernel(float* __restrict__ out, int S, int NT) {
    __shared__ float4 sA[BATCH], sB[BATCH], sC[BATCH];

    int tile = blockIdx.x;
    int b   = tile / (NT * NT);
    int rem = tile - b * (NT * NT);
    int tyT = rem / NT, txT = rem - tyT * NT;
    int tid = threadIdx.x;
    int ix = txT * TS + (tid & (TS - 1));
    int iy = tyT * TS + (tid >> 4);
    float* dst = out + (b * S + iy) * S + ix;

    if (g_full[tile]) { *dst = 1.0f; return; }

    float invS = 1.0f / (float)S;
    float px = (2.0f * (float)ix + 1.0f) * invS - 1.0f;
    float py = (2.0f * (float)iy + 1.0f) * invS - 1.0f;

    int n = g_cnt[tile];
    const int* list = g_bins + tile * CAP;

    bool cov = false;
    for (int k0 = 0; k0 < n; k0 += BATCH) {
        int cnt = min(BATCH, n - k0);
        if (tid < cnt) {
            int f = list[k0 + tid];
            sA[tid] = g_triA[f];
        } else if (tid < 2 * cnt) {
            int f = list[k0 + tid - cnt];
            sB[tid - cnt] = g_triB[f];
        } else if (tid < 3 * cnt) {
            int f = list[k0 + tid - 2 * cnt];
            sC[tid - 2 * cnt] = g_triC[f];
        }
        __syncthreads();

        if (!__all_sync(0xFFFFFFFFu, cov)) {
            #pragma unroll 4
            for (int k = 0; k < cnt; k++) {
                float4 A  = sA[k];
                float4 Bq = sB[k];
                float4 C  = sC[k];
                float w0 = (px - A.x)  * A.z  - (py - A.y)  * A.w;
                float w1 = (px - Bq.x) * Bq.z - (py - Bq.y) * Bq.w;
                float w2 = (px - C.x)  * C.z  - (py - C.y)  * C.w;
                bool pos = (w0 >= 0.0f) & (w1 >= 0.0f) & (w2 >= 0.0f);
                bool neg = (w0 <= 0.0f) & (w1 <= 0.0f) & (w2 <= 0.0f);
                cov |= (pos | neg);
            }
        }
        if (__syncthreads_and((int)cov)) break;   // also guards smem reuse
    }
    *dst = cov ? 1.0f : 0.0f;
}

extern "C" void kernel_launch(void* const* d_in, const int* in_sizes, int n_in,
                              void* d_out, int out_size) {
    const float* verts = (const float*)d_in[0];   // [B,V,3] fp32
    const int*   faces = (const int*)d_in[1];     // [B,F,3] int32
    const float* cams  = (const float*)d_in[2];   // [B,3]   fp32

    int B = in_sizes[2] / 3;
    int V = in_sizes[0] / (3 * B);
    int F = in_sizes[1] / (3 * B);
    int S = 256;
    {   // derive S from out_size (S*S = out_size/B, S a power of two)
        int ss = out_size / B;
        int s = 1;
        while (s * s < ss) s <<= 1;
        if (s * s == ss) S = s;
    }
    int NT = S / TS;

    float* out = (float*)d_out;

    int nset = max(B * V, MAXTILES);
    setup_kernel<<<(nset + 255) / 256, 256>>>(verts, cams, B, V);
    int binCTAs = (B * F + 8 * TPW - 1) / (8 * TPW);   // 8 warps/CTA, TPW tris/warp
    bin_kernel<<<binCTAs, 256>>>(faces, B, V, F, S, NT);
    raster_kernel<<<B * NT * NT, 256>>>(out, S, NT);
}

// round 8
// speedup vs baseline: 4.8736x; 1.0065x over previous
#include <cuda_runtime.h>

// ---- static scratch (allocation-free; zero-initialized at module load) ----
#define MAX_BV    65536            // B*V vertices
#define MAX_BF    32768            // B*F faces
#define TS        16               // tile size in pixels
#define MAXTILES  1024             // B * (S/TS)^2  (2*256 = 512 used)
#define CAP       8192             // per-tile list capacity (>= F)
#define BATCH     64               // triangles staged per smem batch
#define TPW       8                // triangles per warp in binner

__device__ float4 g_triA[MAX_BF];  // (v1x, v1y, dY0, dX0)
__device__ float4 g_triB[MAX_BF];  // (v2x, v2y, dY1, dX1)
__device__ float4 g_triC[MAX_BF];  // (v0x, v0y, dY2, dX2)
__device__ int    g_cnt[MAXTILES];   // reset by raster each run
__device__ int    g_full[MAXTILES];  // reset by raster each run
__device__ int    g_bins[MAXTILES * CAP];

// Reference-identical projection of one vertex.
__device__ __forceinline__ float2 project_vert(const float* __restrict__ verts,
                                               const float* __restrict__ cams,
                                               int b, int vi) {
    float f  = cams[b * 3 + 0];
    float cx = cams[b * 3 + 1];
    float cy = cams[b * 3 + 2];
    float image_size = cams[1] * 2.0f;   // cams[0,1] * 2 per reference
    const float* p = verts + vi * 3;
    float x = p[0], y = p[1], z = p[2];
    float px = f * x / z + cx;
    float py = f * y / z + cy;
    return make_float2(px / image_size * 2.0f - 1.0f,
                       py / image_size * 2.0f - 1.0f);
}

struct TriBin {
    bool  ok;
    int   tx0, ty0, tbase, sx, ntiles;
    float kx[3], ky[3], kc[3];
    float2 v0, v1, v2;
};

__device__ __forceinline__ TriBin tri_setup(const int* __restrict__ faces,
                                            const float* __restrict__ verts,
                                            const float* __restrict__ cams,
                                            int t, int V, int F, int S, int NT) {
    TriBin r; r.ok = false;
    int b = t / F;
    const int* fv = faces + t * 3;
    float2 v0 = project_vert(verts, cams, b, b * V + fv[0]);
    float2 v1 = project_vert(verts, cams, b, b * V + fv[1]);
    float2 v2 = project_vert(verts, cams, b, b * V + fv[2]);
    float area = (v1.x - v0.x) * (v2.y - v0.y)
               - (v1.y - v0.y) * (v2.x - v0.x);
    if (!(fabsf(area) > 1e-12f)) return r;

    float minx = fminf(v0.x, fminf(v1.x, v2.x));
    float maxx = fmaxf(v0.x, fmaxf(v1.x, v2.x));
    float miny = fminf(v0.y, fminf(v1.y, v2.y));
    float maxy = fmaxf(v0.y, fmaxf(v1.y, v2.y));
    float half = 0.5f * (float)S;
    int x0 = max(0,     (int)floorf((minx + 1.0f) * half - 0.5f) - 1);
    int x1 = min(S - 1, (int)ceilf ((maxx + 1.0f) * half - 0.5f) + 1);
    int y0 = max(0,     (int)floorf((miny + 1.0f) * half - 0.5f) - 1);
    int y1 = min(S - 1, (int)ceilf ((maxy + 1.0f) * half - 0.5f) + 1);
    if (x1 < x0 || y1 < y0) return r;

    r.ok = true;
    r.v0 = v0; r.v1 = v1; r.v2 = v2;
    r.tx0 = x0 / TS; r.ty0 = y0 / TS;
    r.tbase = b * NT * NT;
    r.sx = x1 / TS - r.tx0 + 1;
    r.ntiles = r.sx * (y1 / TS - r.ty0 + 1);

    float ss = area > 0.0f ? -1.0f : 1.0f;   // interior: ss*w >= 0
    float axv[3] = {v1.x, v2.x, v0.x};
    float ayv[3] = {v1.y, v2.y, v0.y};
    float dXv[3] = {v2.x - v1.x, v0.x - v2.x, v1.x - v0.x};
    float dYv[3] = {v2.y - v1.y, v0.y - v2.y, v1.y - v0.y};
#pragma unroll
    for (int e = 0; e < 3; e++) {
        r.kx[e] = ss * dYv[e];
        r.ky[e] = -ss * dXv[e];
        r.kc[e] = ss * (ayv[e] * dXv[e] - axv[e] * dYv[e]);
    }
    return r;
}

// Corner-based tile classification: 0 = cull, 1 = list, 2 = full-cover.
__device__ __forceinline__ int tile_class(const TriBin& r, int tx, int ty,
                                          float invS, float span) {
    float cx0 = (2.0f * (float)(tx * TS) + 1.0f) * invS - 1.0f;
    float cy0 = (2.0f * (float)(ty * TS) + 1.0f) * invS - 1.0f;
    const float MARGIN = 1e-4f;
    bool full = true, cull = false;
#pragma unroll
    for (int e = 0; e < 3; e++) {
        float base = r.kx[e] * cx0 + r.ky[e] * cy0 + r.kc[e];
        float dxs = r.kx[e] * span, dys = r.ky[e] * span;
        float tmin = base + fminf(dxs, 0.0f) + fminf(dys, 0.0f);
        float tmax = base + fmaxf(dxs, 0.0f) + fmaxf(dys, 0.0f);
        full = full && (tmin >= MARGIN);
        cull = cull || (tmax <= -MARGIN);
    }
    return full ? 2 : (cull ? 0 : 1);
}

// Warp-parallel binning. Phase 1: classify tiles, count into smem, record
// each lane's "list" decisions in a bitmask (round -> bit). Phase 2: replay
// the bitmask and scatter — no recomputation.
__global__ void __launch_bounds__(256)
bin_kernel(const int* __restrict__ faces, const float* __restrict__ verts,
           const float* __restrict__ cams, int B, int V, int F, int S, int NT) {
    __shared__ int s_cnt[MAXTILES];
    __shared__ int s_base[MAXTILES];
    for (int i = threadIdx.x; i < MAXTILES; i += 256) s_cnt[i] = 0;
    __syncthreads();

    int BF = B * F;
    int warpsTotal = gridDim.x * 8;
    int warpId = blockIdx.x * 8 + (threadIdx.x >> 5);
    int lane = threadIdx.x & 31;
    float invS = 1.0f / (float)S;
    float span = 30.0f * invS;   // ndc span between tile corner pixel centers

    unsigned int lmask[TPW];     // bit i: tile (i*32+lane) is "list"
    unsigned int lmeta[TPW];     // packed tx0|ty0<<5|sx<<10|tbase<<15
#pragma unroll
    for (int k = 0; k < TPW; k++) { lmask[k] = 0u; lmeta[k] = 0u; }

    // phase 1: classify + count + coefficient emit + full flags
    for (int k = 0; k < TPW; k++) {
        int t = warpId + k * warpsTotal;
        if (t >= BF) break;
        TriBin r = tri_setup(faces, verts, cams, t, V, F, S, NT);
        if (!r.ok) continue;
        if (lane == 0) {
            g_triA[t] = make_float4(r.v1.x, r.v1.y, r.v2.y - r.v1.y, r.v2.x - r.v1.x);
            g_triB[t] = make_float4(r.v2.x, r.v2.y, r.v0.y - r.v2.y, r.v0.x - r.v2.x);
            g_triC[t] = make_float4(r.v0.x, r.v0.y, r.v1.y - r.v0.y, r.v1.x - r.v0.x);
        }
        lmeta[k] = (unsigned int)r.tx0 | ((unsigned int)r.ty0 << 5)
                 | ((unsigned int)r.sx << 10) | ((unsigned int)r.tbase << 15);
        unsigned int m = 0u;
        for (int i = lane; i < r.ntiles; i += 32) {
            int tx = r.tx0 + (i % r.sx);
            int ty = r.ty0 + (i / r.sx);
            int tile = r.tbase + ty * NT + tx;
            int c = tile_class(r, tx, ty, invS, span);
            if (c == 2)      g_full[tile] = 1;
            else if (c == 1) { m |= 1u << (i >> 5); atomicAdd(&s_cnt[tile], 1); }
        }
        lmask[k] = m;
    }
    __syncthreads();
    for (int i = threadIdx.x; i < MAXTILES; i += 256) {
        int c = s_cnt[i];
        s_base[i] = c ? atomicAdd(&g_cnt[i], c) : 0;
        s_cnt[i] = 0;
    }
    __syncthreads();
    // phase 2: replay bitmasks and scatter
    for (int k = 0; k < TPW; k++) {
        unsigned int m = lmask[k];
        if (!m) continue;
        int t = warpId + k * warpsTotal;
        unsigned int me = lmeta[k];
        int tx0   = me & 31;
        int ty0   = (me >> 5) & 31;
        int sx    = (me >> 10) & 31;
        int tbase = me >> 15;
        while (m) {
            int bit = __ffs(m) - 1;
            m &= m - 1;
            int i = (bit << 5) + lane;
            int tx = tx0 + (i % sx);
            int ty = ty0 + (i / sx);
            int tile = tbase + ty * NT + tx;
            int pos = s_base[tile] + atomicAdd(&s_cnt[tile], 1);
            g_bins[tile * CAP + pos] = t;
        }
    }
}

// One CTA per (batch, 16x16 tile); one thread per pixel. Full tiles exit
// immediately; others scan smem-staged batches with CTA/warp early exit.
// Each CTA resets its tile's g_cnt/g_full for the next graph replay.
// Edge test byte-identical to the R1-passing kernel.
__global__ void __launch_bounds__(256)
raster_kernel(float* __restrict__ out, int S, int NT) {
    __shared__ float4 sA[BATCH], sB[BATCH], sC[BATCH];

    int tile = blockIdx.x;
    int b   = tile / (NT * NT);
    int rem = tile - b * (NT * NT);
    int tyT = rem / NT, txT = rem - tyT * NT;
    int tid = threadIdx.x;
    int ix = txT * TS + (tid & (TS - 1));
    int iy = tyT * TS + (tid >> 4);
    float* dst = out + (b * S + iy) * S + ix;

    int n    = g_cnt[tile];
    int full = g_full[tile];
    __syncthreads();                       // all reads done before reset
    if (tid == 0) { g_cnt[tile] = 0; g_full[tile] = 0; }

    if (full) { *dst = 1.0f; return; }

    float invS = 1.0f / (float)S;
    float px = (2.0f * (float)ix + 1.0f) * invS - 1.0f;
    float py = (2.0f * (float)iy + 1.0f) * invS - 1.0f;

    const int* list = g_bins + tile * CAP;

    bool cov = false;
    for (int k0 = 0; k0 < n; k0 += BATCH) {
        int cnt = min(BATCH, n - k0);
        if (tid < cnt) {
            int f = list[k0 + tid];
            sA[tid] = g_triA[f];
        } else if (tid < 2 * cnt) {
            int f = list[k0 + tid - cnt];
            sB[tid - cnt] = g_triB[f];
        } else if (tid < 3 * cnt) {
            int f = list[k0 + tid - 2 * cnt];
            sC[tid - 2 * cnt] = g_triC[f];
        }
        __syncthreads();

        if (!__all_sync(0xFFFFFFFFu, cov)) {
            #pragma unroll 4
            for (int k = 0; k < cnt; k++) {
                float4 A  = sA[k];
                float4 Bq = sB[k];
                float4 C  = sC[k];
                float w0 = (px - A.x)  * A.z  - (py - A.y)  * A.w;
                float w1 = (px - Bq.x) * Bq.z - (py - Bq.y) * Bq.w;
                float w2 = (px - C.x)  * C.z  - (py - C.y)  * C.w;
                bool pos = (w0 >= 0.0f) & (w1 >= 0.0f) & (w2 >= 0.0f);
                bool neg = (w0 <= 0.0f) & (w1 <= 0.0f) & (w2 <= 0.0f);
                cov |= (pos | neg);
            }
        }
        if (__syncthreads_and((int)cov)) break;   // also guards smem reuse
    }
    *dst = cov ? 1.0f : 0.0f;
}

extern "C" void kernel_launch(void* const* d_in, const int* in_sizes, int n_in,
                              void* d_out, int out_size) {
    const float* verts = (const float*)d_in[0];   // [B,V,3] fp32
    const int*   faces = (const int*)d_in[1];     // [B,F,3] int32
    const float* cams  = (const float*)d_in[2];   // [B,3]   fp32

    int B = in_sizes[2] / 3;
    int V = in_sizes[0] / (3 * B);
    int F = in_sizes[1] / (3 * B);
    int S = 256;
    {   // derive S from out_size (S*S = out_size/B, S a power of two)
        int ss = out_size / B;
        int s = 1;
        while (s * s < ss) s <<= 1;
        if (s * s == ss) S = s;
    }
    int NT = S / TS;

    float* out = (float*)d_out;

    int binCTAs = (B * F + 8 * TPW - 1) / (8 * TPW);   // 8 warps/CTA
    bin_kernel<<<binCTAs, 256>>>(faces, verts, cams, B, V, F, S, NT);
    raster_kernel<<<B * NT * NT, 256>>>(out, S, NT);
}

// round 9
// speedup vs baseline: 6.9396x; 1.4239x over previous
#include <cuda_runtime.h>

// ---- static scratch (allocation-free; zero-initialized at module load) ----
#define MAX_BF    32768            // B*F faces
#define TS        16               // tile size in pixels
#define MAXTILES  1024             // B * (S/TS)^2  (2*256 = 512 used)
#define CAP       8192             // per-tile list capacity (>= F)
#define BATCH     64               // triangles staged per smem batch
#define TPW       8                // triangles per warp in binner (lane-parallel)

__device__ float4 g_triA[MAX_BF];  // (v1x, v1y, dY0, dX0)
__device__ float4 g_triB[MAX_BF];  // (v2x, v2y, dY1, dX1)
__device__ float4 g_triC[MAX_BF];  // (v0x, v0y, dY2, dX2)
__device__ int    g_cnt[MAXTILES];   // reset by raster each run
__device__ int    g_full[MAXTILES];  // reset by raster each run
__device__ int    g_bins[MAXTILES * CAP];

// Reference-identical projection of one vertex.
__device__ __forceinline__ float2 project_vert(const float* __restrict__ verts,
                                               const float* __restrict__ cams,
                                               int b, int vi) {
    float f  = cams[b * 3 + 0];
    float cx = cams[b * 3 + 1];
    float cy = cams[b * 3 + 2];
    float image_size = cams[1] * 2.0f;   // cams[0,1] * 2 per reference
    const float* p = verts + vi * 3;
    float x = p[0], y = p[1], z = p[2];
    float px = f * x / z + cx;
    float py = f * y / z + cy;
    return make_float2(px / image_size * 2.0f - 1.0f,
                       py / image_size * 2.0f - 1.0f);
}

struct TriBin {
    int   ok;
    int   tx0, ty0, tbase, sx, ntiles;
    float kx[3], ky[3], kc[3];
};

// Full per-triangle setup; also emits the raster coefficient records.
__device__ __forceinline__ TriBin tri_setup(const int* __restrict__ faces,
                                            const float* __restrict__ verts,
                                            const float* __restrict__ cams,
                                            int t, int V, int F, int S, int NT) {
    TriBin r; r.ok = 0;
    int b = t / F;
    const int* fv = faces + t * 3;
    float2 v0 = project_vert(verts, cams, b, b * V + fv[0]);
    float2 v1 = project_vert(verts, cams, b, b * V + fv[1]);
    float2 v2 = project_vert(verts, cams, b, b * V + fv[2]);
    float area = (v1.x - v0.x) * (v2.y - v0.y)
               - (v1.y - v0.y) * (v2.x - v0.x);
    if (!(fabsf(area) > 1e-12f)) return r;

    float minx = fminf(v0.x, fminf(v1.x, v2.x));
    float maxx = fmaxf(v0.x, fmaxf(v1.x, v2.x));
    float miny = fminf(v0.y, fminf(v1.y, v2.y));
    float maxy = fmaxf(v0.y, fmaxf(v1.y, v2.y));
    float half = 0.5f * (float)S;
    int x0 = max(0,     (int)floorf((minx + 1.0f) * half - 0.5f) - 1);
    int x1 = min(S - 1, (int)ceilf ((maxx + 1.0f) * half - 0.5f) + 1);
    int y0 = max(0,     (int)floorf((miny + 1.0f) * half - 0.5f) - 1);
    int y1 = min(S - 1, (int)ceilf ((maxy + 1.0f) * half - 0.5f) + 1);
    if (x1 < x0 || y1 < y0) return r;

    r.ok = 1;
    r.tx0 = x0 / TS; r.ty0 = y0 / TS;
    r.tbase = b * NT * NT;
    r.sx = x1 / TS - r.tx0 + 1;
    r.ntiles = r.sx * (y1 / TS - r.ty0 + 1);

    g_triA[t] = make_float4(v1.x, v1.y, v2.y - v1.y, v2.x - v1.x);
    g_triB[t] = make_float4(v2.x, v2.y, v0.y - v2.y, v0.x - v2.x);
    g_triC[t] = make_float4(v0.x, v0.y, v1.y - v0.y, v1.x - v0.x);

    float ss = area > 0.0f ? -1.0f : 1.0f;   // interior: ss*w >= 0
    float axv[3] = {v1.x, v2.x, v0.x};
    float ayv[3] = {v1.y, v2.y, v0.y};
    float dXv[3] = {v2.x - v1.x, v0.x - v2.x, v1.x - v0.x};
    float dYv[3] = {v2.y - v1.y, v0.y - v2.y, v1.y - v0.y};
#pragma unroll
    for (int e = 0; e < 3; e++) {
        r.kx[e] = ss * dYv[e];
        r.ky[e] = -ss * dXv[e];
        r.kc[e] = ss * (ayv[e] * dXv[e] - axv[e] * dYv[e]);
    }
    return r;
}

// Corner-based tile classification on broadcast scalars: 0 cull, 1 list, 2 full.
__device__ __forceinline__ int tile_class_s(
    const float* kx, const float* ky, const float* kc,
    int tx, int ty, float invS, float span)
{
    float cx0 = (2.0f * (float)(tx * TS) + 1.0f) * invS - 1.0f;
    float cy0 = (2.0f * (float)(ty * TS) + 1.0f) * invS - 1.0f;
    const float MARGIN = 1e-4f;
    bool full = true, cull = false;
#pragma unroll
    for (int e = 0; e < 3; e++) {
        float base = kx[e] * cx0 + ky[e] * cy0 + kc[e];
        float dxs = kx[e] * span, dys = ky[e] * span;
        float tmin = base + fminf(dxs, 0.0f) + fminf(dys, 0.0f);
        float tmax = base + fmaxf(dxs, 0.0f) + fmaxf(dys, 0.0f);
        full = full && (tmin >= MARGIN);
        cull = cull || (tmax <= -MARGIN);
    }
    return full ? 2 : (cull ? 0 : 1);
}

// Warp-parallel binning, lane-parallel setup: each warp owns TPW consecutive
// triangles; lane l < TPW runs tri_setup for triangle base+l. Classification
// loops the TPW triangles, broadcasting coefficients via shfl; lanes split
// the tile span. Phase 2 replays recorded bitmasks and scatters.
__global__ void __launch_bounds__(256)
bin_kernel(const int* __restrict__ faces, const float* __restrict__ verts,
           const float* __restrict__ cams, int B, int V, int F, int S, int NT) {
    __shared__ int s_cnt[MAXTILES];
    __shared__ int s_base[MAXTILES];
    for (int i = threadIdx.x; i < MAXTILES; i += 256) s_cnt[i] = 0;
    __syncthreads();

    int BF = B * F;
    int warpId = blockIdx.x * 8 + (threadIdx.x >> 5);
    int warpBase = warpId * TPW;
    int lane = threadIdx.x & 31;
    float invS = 1.0f / (float)S;
    float span = 30.0f * invS;   // ndc span between tile corner pixel centers
    const unsigned int FULLM = 0xFFFFFFFFu;

    // lane-parallel setup for this warp's TPW triangles
    TriBin mine; mine.ok = 0;
    if (lane < TPW && warpBase + lane < BF)
        mine = tri_setup(faces, verts, cams, warpBase + lane, V, F, S, NT);

    unsigned int lmask[TPW];     // bit i: tile (i*32+lane) of triangle k is "list"
    unsigned int lmeta[TPW];     // packed tx0|ty0<<5|sx<<10|tbase<<15
#pragma unroll
    for (int k = 0; k < TPW; k++) { lmask[k] = 0u; lmeta[k] = 0u; }

    // phase 1: classify + count + full flags
#pragma unroll
    for (int k = 0; k < TPW; k++) {
        if (warpBase + k >= BF) break;
        if (!__shfl_sync(FULLM, mine.ok, k)) continue;
        float kx[3], ky[3], kc[3];
#pragma unroll
        for (int e = 0; e < 3; e++) {
            kx[e] = __shfl_sync(FULLM, mine.kx[e], k);
            ky[e] = __shfl_sync(FULLM, mine.ky[e], k);
            kc[e] = __shfl_sync(FULLM, mine.kc[e], k);
        }
        int tx0    = __shfl_sync(FULLM, mine.tx0, k);
        int ty0    = __shfl_sync(FULLM, mine.ty0, k);
        int sx     = __shfl_sync(FULLM, mine.sx, k);
        int ntiles = __shfl_sync(FULLM, mine.ntiles, k);
        int tbase  = __shfl_sync(FULLM, mine.tbase, k);
        lmeta[k] = (unsigned int)tx0 | ((unsigned int)ty0 << 5)
                 | ((unsigned int)sx << 10) | ((unsigned int)tbase << 15);
        unsigned int m = 0u;
        for (int i = lane; i < ntiles; i += 32) {
            int tx = tx0 + (i % sx);
            int ty = ty0 + (i / sx);
            int tile = tbase + ty * NT + tx;
            int c = tile_class_s(kx, ky, kc, tx, ty, invS, span);
            if (c == 2)      g_full[tile] = 1;
            else if (c == 1) { m |= 1u << (i >> 5); atomicAdd(&s_cnt[tile], 1); }
        }
        lmask[k] = m;
    }
    __syncthreads();
    for (int i = threadIdx.x; i < MAXTILES; i += 256) {
        int c = s_cnt[i];
        s_base[i] = c ? atomicAdd(&g_cnt[i], c) : 0;
        s_cnt[i] = 0;
    }
    __syncthreads();
    // phase 2: replay bitmasks and scatter
#pragma unroll
    for (int k = 0; k < TPW; k++) {
        unsigned int m = lmask[k];
        if (!m) continue;
        int t = warpBase + k;
        unsigned int me = lmeta[k];
        int tx0   = me & 31;
        int ty0   = (me >> 5) & 31;
        int sx    = (me >> 10) & 31;
        int tbase = me >> 15;
        while (m) {
            int bit = __ffs(m) - 1;
            m &= m - 1;
            int i = (bit << 5) + lane;
            int tx = tx0 + (i % sx);
            int ty = ty0 + (i / sx);
            int tile = tbase + ty * NT + tx;
            int pos = s_base[tile] + atomicAdd(&s_cnt[tile], 1);
            g_bins[tile * CAP + pos] = t;
        }
    }
}

// One CTA per (batch, 16x16 tile); one thread per pixel. Full tiles exit
// immediately; others scan smem-staged batches with CTA/warp early exit.
// Each CTA resets its tile's g_cnt/g_full for the next graph replay.
// Edge test byte-identical to the R1-passing kernel.
__global__ void __launch_bounds__(256)
raster_kernel(float* __restrict__ out, int S, int NT) {
    __shared__ float4 sA[BATCH], sB[BATCH], sC[BATCH];

    int tile = blockIdx.x;
    int b   = tile / (NT * NT);
    int rem = tile - b * (NT * NT);
    int tyT = rem / NT, txT = rem - tyT * NT;
    int tid = threadIdx.x;
    int ix = txT * TS + (tid & (TS - 1));
    int iy = tyT * TS + (tid >> 4);
    float* dst = out + (b * S + iy) * S + ix;

    int n    = g_cnt[tile];
    int full = g_full[tile];
    __syncthreads();                       // all reads done before reset
    if (tid == 0) { g_cnt[tile] = 0; g_full[tile] = 0; }

    if (full) { *dst = 1.0f; return; }

    float invS = 1.0f / (float)S;
    float px = (2.0f * (float)ix + 1.0f) * invS - 1.0f;
    float py = (2.0f * (float)iy + 1.0f) * invS - 1.0f;

    const int* list = g_bins + tile * CAP;

    bool cov = false;
    for (int k0 = 0; k0 < n; k0 += BATCH) {
        int cnt = min(BATCH, n - k0);
        if (tid < cnt) {
            int f = list[k0 + tid];
            sA[tid] = g_triA[f];
        } else if (tid < 2 * cnt) {
            int f = list[k0 + tid - cnt];
            sB[tid - cnt] = g_triB[f];
        } else if (tid < 3 * cnt) {
            int f = list[k0 + tid - 2 * cnt];
            sC[tid - 2 * cnt] = g_triC[f];
        }
        __syncthreads();

        if (!__all_sync(0xFFFFFFFFu, cov)) {
            #pragma unroll 4
            for (int k = 0; k < cnt; k++) {
                float4 A  = sA[k];
                float4 Bq = sB[k];
                float4 C  = sC[k];
                float w0 = (px - A.x)  * A.z  - (py - A.y)  * A.w;
                float w1 = (px - Bq.x) * Bq.z - (py - Bq.y) * Bq.w;
                float w2 = (px - C.x)  * C.z  - (py - C.y)  * C.w;
                bool pos = (w0 >= 0.0f) & (w1 >= 0.0f) & (w2 >= 0.0f);
                bool neg = (w0 <= 0.0f) & (w1 <= 0.0f) & (w2 <= 0.0f);
                cov |= (pos | neg);
            }
        }
        if (__syncthreads_and((int)cov)) break;   // also guards smem reuse
    }
    *dst = cov ? 1.0f : 0.0f;
}

extern "C" void kernel_launch(void* const* d_in, const int* in_sizes, int n_in,
                              void* d_out, int out_size) {
    const float* verts = (const float*)d_in[0];   // [B,V,3] fp32
    const int*   faces = (const int*)d_in[1];     // [B,F,3] int32
    const float* cams  = (const float*)d_in[2];   // [B,3]   fp32

    int B = in_sizes[2] / 3;
    int V = in_sizes[0] / (3 * B);
    int F = in_sizes[1] / (3 * B);
    int S = 256;
    {   // derive S from out_size (S*S = out_size/B, S a power of two)
        int ss = out_size / B;
        int s = 1;
        while (s * s < ss) s <<= 1;
        if (s * s == ss) S = s;
    }
    int NT = S / TS;

    float* out = (float*)d_out;

    int binCTAs = (B * F + 8 * TPW - 1) / (8 * TPW);   // 8 warps/CTA
    bin_kernel<<<binCTAs, 256>>>(faces, verts, cams, B, V, F, S, NT);
    raster_kernel<<<B * NT * NT, 256>>>(out, S, NT);
}

// round 10
// speedup vs baseline: 7.1046x; 1.0238x over previous
#include <cuda_runtime.h>

// ---- static scratch (allocation-free; zero-initialized at module load) ----
#define MAX_BF    32768            // B*F faces
#define TS        16               // tile size in pixels
#define MAXTILES  1024             // B * (S/TS)^2  (2*256 = 512 used)
#define CAP       8192             // per-tile list capacity (>= F)
#define BATCH     64               // triangles staged per smem batch
#define TPW       4                // triangles per warp in binner (lane-parallel)

__device__ float4 g_triA[MAX_BF];  // (v1x, v1y, dY0, dX0)
__device__ float4 g_triB[MAX_BF];  // (v2x, v2y, dY1, dX1)
__device__ float4 g_triC[MAX_BF];  // (v0x, v0y, dY2, dX2)
__device__ int    g_cnt[MAXTILES];   // reset by raster each run
__device__ int    g_full[MAXTILES];  // reset by raster each run
__device__ int    g_bins[MAXTILES * CAP];

// Reference-identical projection of one vertex.
__device__ __forceinline__ float2 project_vert(const float* __restrict__ verts,
                                               const float* __restrict__ cams,
                                               int b, int vi) {
    float f  = cams[b * 3 + 0];
    float cx = cams[b * 3 + 1];
    float cy = cams[b * 3 + 2];
    float image_size = cams[1] * 2.0f;   // cams[0,1] * 2 per reference
    const float* p = verts + vi * 3;
    float x = p[0], y = p[1], z = p[2];
    float px = f * x / z + cx;
    float py = f * y / z + cy;
    return make_float2(px / image_size * 2.0f - 1.0f,
                       py / image_size * 2.0f - 1.0f);
}

struct TriBin {
    int   ok;
    int   tx0, ty0, tbase, sx, ntiles;
    float kx[3], ky[3], kc[3];
};

// Full per-triangle setup; also emits the raster coefficient records.
__device__ __forceinline__ TriBin tri_setup(const int* __restrict__ faces,
                                            const float* __restrict__ verts,
                                            const float* __restrict__ cams,
                                            int t, int V, int F, int S, int NT) {
    TriBin r; r.ok = 0;
    int b = t / F;
    const int* fv = faces + t * 3;
    float2 v0 = project_vert(verts, cams, b, b * V + fv[0]);
    float2 v1 = project_vert(verts, cams, b, b * V + fv[1]);
    float2 v2 = project_vert(verts, cams, b, b * V + fv[2]);
    float area = (v1.x - v0.x) * (v2.y - v0.y)
               - (v1.y - v0.y) * (v2.x - v0.x);
    if (!(fabsf(area) > 1e-12f)) return r;

    float minx = fminf(v0.x, fminf(v1.x, v2.x));
    float maxx = fmaxf(v0.x, fmaxf(v1.x, v2.x));
    float miny = fminf(v0.y, fminf(v1.y, v2.y));
    float maxy = fmaxf(v0.y, fmaxf(v1.y, v2.y));
    float half = 0.5f * (float)S;
    int x0 = max(0,     (int)floorf((minx + 1.0f) * half - 0.5f) - 1);
    int x1 = min(S - 1, (int)ceilf ((maxx + 1.0f) * half - 0.5f) + 1);
    int y0 = max(0,     (int)floorf((miny + 1.0f) * half - 0.5f) - 1);
    int y1 = min(S - 1, (int)ceilf ((maxy + 1.0f) * half - 0.5f) + 1);
    if (x1 < x0 || y1 < y0) return r;

    r.ok = 1;
    r.tx0 = x0 / TS; r.ty0 = y0 / TS;
    r.tbase = b * NT * NT;
    r.sx = x1 / TS - r.tx0 + 1;
    r.ntiles = r.sx * (y1 / TS - r.ty0 + 1);

    g_triA[t] = make_float4(v1.x, v1.y, v2.y - v1.y, v2.x - v1.x);
    g_triB[t] = make_float4(v2.x, v2.y, v0.y - v2.y, v0.x - v2.x);
    g_triC[t] = make_float4(v0.x, v0.y, v1.y - v0.y, v1.x - v0.x);

    float ss = area > 0.0f ? -1.0f : 1.0f;   // interior: ss*w >= 0
    float axv[3] = {v1.x, v2.x, v0.x};
    float ayv[3] = {v1.y, v2.y, v0.y};
    float dXv[3] = {v2.x - v1.x, v0.x - v2.x, v1.x - v0.x};
    float dYv[3] = {v2.y - v1.y, v0.y - v2.y, v1.y - v0.y};
#pragma unroll
    for (int e = 0; e < 3; e++) {
        r.kx[e] = ss * dYv[e];
        r.ky[e] = -ss * dXv[e];
        r.kc[e] = ss * (ayv[e] * dXv[e] - axv[e] * dYv[e]);
    }
    return r;
}

// Corner-based tile classification on broadcast scalars: 0 cull, 1 list, 2 full.
__device__ __forceinline__ int tile_class_s(
    const float* kx, const float* ky, const float* kc,
    int tx, int ty, float invS, float span)
{
    float cx0 = (2.0f * (float)(tx * TS) + 1.0f) * invS - 1.0f;
    float cy0 = (2.0f * (float)(ty * TS) + 1.0f) * invS - 1.0f;
    const float MARGIN = 1e-4f;
    bool full = true, cull = false;
#pragma unroll
    for (int e = 0; e < 3; e++) {
        float base = kx[e] * cx0 + ky[e] * cy0 + kc[e];
        float dxs = kx[e] * span, dys = ky[e] * span;
        float tmin = base + fminf(dxs, 0.0f) + fminf(dys, 0.0f);
        float tmax = base + fmaxf(dxs, 0.0f) + fmaxf(dys, 0.0f);
        full = full && (tmin >= MARGIN);
        cull = cull || (tmax <= -MARGIN);
    }
    return full ? 2 : (cull ? 0 : 1);
}

// Warp-parallel binning, lane-parallel setup (lane l < TPW owns triangle
// base+l). Phase 1: classify/count via shfl broadcast; phase 2: bitmask replay.
__global__ void __launch_bounds__(256)
bin_kernel(const int* __restrict__ faces, const float* __restrict__ verts,
           const float* __restrict__ cams, int B, int V, int F, int S, int NT) {
    __shared__ int s_cnt[MAXTILES];
    __shared__ int s_base[MAXTILES];
    for (int i = threadIdx.x; i < MAXTILES; i += 256) s_cnt[i] = 0;
    __syncthreads();

    int BF = B * F;
    int warpId = blockIdx.x * 8 + (threadIdx.x >> 5);
    int warpBase = warpId * TPW;
    int lane = threadIdx.x & 31;
    float invS = 1.0f / (float)S;
    float span = 30.0f * invS;   // ndc span between tile corner pixel centers
    const unsigned int FULLM = 0xFFFFFFFFu;

    TriBin mine; mine.ok = 0;
    if (lane < TPW && warpBase + lane < BF)
        mine = tri_setup(faces, verts, cams, warpBase + lane, V, F, S, NT);

    unsigned int lmask[TPW];     // bit i: tile (i*32+lane) of triangle k is "list"
    unsigned int lmeta[TPW];     // packed tx0|ty0<<5|sx<<10|tbase<<15
#pragma unroll
    for (int k = 0; k < TPW; k++) { lmask[k] = 0u; lmeta[k] = 0u; }

    // phase 1: classify + count + full flags
#pragma unroll
    for (int k = 0; k < TPW; k++) {
        if (warpBase + k >= BF) break;
        if (!__shfl_sync(FULLM, mine.ok, k)) continue;
        float kx[3], ky[3], kc[3];
#pragma unroll
        for (int e = 0; e < 3; e++) {
            kx[e] = __shfl_sync(FULLM, mine.kx[e], k);
            ky[e] = __shfl_sync(FULLM, mine.ky[e], k);
            kc[e] = __shfl_sync(FULLM, mine.kc[e], k);
        }
        int tx0    = __shfl_sync(FULLM, mine.tx0, k);
        int ty0    = __shfl_sync(FULLM, mine.ty0, k);
        int sx     = __shfl_sync(FULLM, mine.sx, k);
        int ntiles = __shfl_sync(FULLM, mine.ntiles, k);
        int tbase  = __shfl_sync(FULLM, mine.tbase, k);
        lmeta[k] = (unsigned int)tx0 | ((unsigned int)ty0 << 5)
                 | ((unsigned int)sx << 10) | ((unsigned int)tbase << 15);
        unsigned int m = 0u;
        for (int i = lane; i < ntiles; i += 32) {
            int tx = tx0 + (i % sx);
            int ty = ty0 + (i / sx);
            int tile = tbase + ty * NT + tx;
            int c = tile_class_s(kx, ky, kc, tx, ty, invS, span);
            if (c == 2)      g_full[tile] = 1;
            else if (c == 1) { m |= 1u << (i >> 5); atomicAdd(&s_cnt[tile], 1); }
        }
        lmask[k] = m;
    }
    __syncthreads();
    for (int i = threadIdx.x; i < MAXTILES; i += 256) {
        int c = s_cnt[i];
        s_base[i] = c ? atomicAdd(&g_cnt[i], c) : 0;
        s_cnt[i] = 0;
    }
    __syncthreads();
    // phase 2: replay bitmasks and scatter
#pragma unroll
    for (int k = 0; k < TPW; k++) {
        unsigned int m = lmask[k];
        if (!m) continue;
        int t = warpBase + k;
        unsigned int me = lmeta[k];
        int tx0   = me & 31;
        int ty0   = (me >> 5) & 31;
        int sx    = (me >> 10) & 31;
        int tbase = me >> 15;
        while (m) {
            int bit = __ffs(m) - 1;
            m &= m - 1;
            int i = (bit << 5) + lane;
            int tx = tx0 + (i % sx);
            int ty = ty0 + (i / sx);
            int tile = tbase + ty * NT + tx;
            int pos = s_base[tile] + atomicAdd(&s_cnt[tile], 1);
            g_bins[tile * CAP + pos] = t;
        }
    }
}

// One CTA per (batch, 16x16 tile); one thread per pixel. Full tiles exit
// immediately; others scan smem-staged batches, voting every 8 triangles.
// min/max test form is exactly equivalent to the reference chain on finite
// inputs (min/max are rounding-free; operands are O(1) finite).
__global__ void __launch_bounds__(256)
raster_kernel(float* __restrict__ out, int S, int NT) {
    __shared__ float4 sA[BATCH], sB[BATCH], sC[BATCH];

    int tile = blockIdx.x;
    int b   = tile / (NT * NT);
    int rem = tile - b * (NT * NT);
    int tyT = rem / NT, txT = rem - tyT * NT;
    int tid = threadIdx.x;
    int ix = txT * TS + (tid & (TS - 1));
    int iy = tyT * TS + (tid >> 4);
    float* dst = out + (b * S + iy) * S + ix;

    int n    = g_cnt[tile];
    int full = g_full[tile];
    __syncthreads();                       // all reads done before reset
    if (tid == 0) { g_cnt[tile] = 0; g_full[tile] = 0; }

    if (full) { *dst = 1.0f; return; }

    float invS = 1.0f / (float)S;
    float px = (2.0f * (float)ix + 1.0f) * invS - 1.0f;
    float py = (2.0f * (float)iy + 1.0f) * invS - 1.0f;

    const int* list = g_bins + tile * CAP;
    const unsigned int FULLM = 0xFFFFFFFFu;

    bool cov = false;
    for (int k0 = 0; k0 < n; k0 += BATCH) {
        int cnt = min(BATCH, n - k0);
        if (tid < cnt) {
            int f = list[k0 + tid];
            sA[tid] = g_triA[f];
        } else if (tid < 2 * cnt) {
            int f = list[k0 + tid - cnt];
            sB[tid - cnt] = g_triB[f];
        } else if (tid < 3 * cnt) {
            int f = list[k0 + tid - 2 * cnt];
            sC[tid - 2 * cnt] = g_triC[f];
        }
        __syncthreads();

        for (int kc = 0; kc < cnt && !__all_sync(FULLM, cov); kc += 8) {
            int ke = min(kc + 8, cnt);
            #pragma unroll 8
            for (int k = kc; k < ke; k++) {
                float4 A  = sA[k];
                float4 Bq = sB[k];
                float4 C  = sC[k];
                float w0 = (px - A.x)  * A.z  - (py - A.y)  * A.w;
                float w1 = (px - Bq.x) * Bq.z - (py - Bq.y) * Bq.w;
                float w2 = (px - C.x)  * C.z  - (py - C.y)  * C.w;
                float wmin = fminf(w0, fminf(w1, w2));
                float wmax = fmaxf(w0, fmaxf(w1, w2));
                cov |= (wmin >= 0.0f) | (wmax <= 0.0f);
            }
        }
        if (__syncthreads_and((int)cov)) break;   // also guards smem reuse
    }
    *dst = cov ? 1.0f : 0.0f;
}

extern "C" void kernel_launch(void* const* d_in, const int* in_sizes, int n_in,
                              void* d_out, int out_size) {
    const float* verts = (const float*)d_in[0];   // [B,V,3] fp32
    const int*   faces = (const int*)d_in[1];     // [B,F,3] int32
    const float* cams  = (const float*)d_in[2];   // [B,3]   fp32

    int B = in_sizes[2] / 3;
    int V = in_sizes[0] / (3 * B);
    int F = in_sizes[1] / (3 * B);
    int S = 256;
    {   // derive S from out_size (S*S = out_size/B, S a power of two)
        int ss = out_size / B;
        int s = 1;
        while (s * s < ss) s <<= 1;
        if (s * s == ss) S = s;
    }
    int NT = S / TS;

    float* out = (float*)d_out;

    int binCTAs = (B * F + 8 * TPW - 1) / (8 * TPW);   // 8 warps/CTA
    bin_kernel<<<binCTAs, 256>>>(faces, verts, cams, B, V, F, S, NT);
    raster_kernel<<<B * NT * NT, 256>>>(out, S, NT);
}

// round 11
// speedup vs baseline: 7.5537x; 1.0632x over previous
#include <cuda_runtime.h>

// ---- static scratch (allocation-free; zero-initialized at module load) ----
#define MAX_BF    32768            // B*F faces
#define TS        16               // tile size in pixels
#define MAXTILES  1024             // B * (S/TS)^2  (2*256 = 512 used)
#define CAP       8192             // per-tile list capacity (>= F)
#define BATCH     64               // triangles staged per smem batch
#define TPW       4                // triangles per warp in binner (lane-parallel)
#define NSPLIT    4                // sub-CTAs cooperating on one tile

__device__ float4 g_triA[MAX_BF];  // (v1x, v1y, dY0, dX0)
__device__ float4 g_triB[MAX_BF];  // (v2x, v2y, dY1, dX1)
__device__ float4 g_triC[MAX_BF];  // (v0x, v0y, dY2, dX2)
__device__ int    g_cnt[MAXTILES];    // reset each run (raster)
__device__ int    g_full[MAXTILES];   // reset each run (raster)
__device__ int    g_done[MAXTILES];   // reset each run (raster)
__device__ unsigned int g_mask[MAXTILES * 8];  // 256-bit coverage per tile
__device__ int    g_bins[MAXTILES * CAP];

// Reference-identical projection of one vertex.
__device__ __forceinline__ float2 project_vert(const float* __restrict__ verts,
                                               const float* __restrict__ cams,
                                               int b, int vi) {
    float f  = cams[b * 3 + 0];
    float cx = cams[b * 3 + 1];
    float cy = cams[b * 3 + 2];
    float image_size = cams[1] * 2.0f;   // cams[0,1] * 2 per reference
    const float* p = verts + vi * 3;
    float x = p[0], y = p[1], z = p[2];
    float px = f * x / z + cx;
    float py = f * y / z + cy;
    return make_float2(px / image_size * 2.0f - 1.0f,
                       py / image_size * 2.0f - 1.0f);
}

struct TriBin {
    int   ok;
    int   tx0, ty0, tbase, sx, ntiles;
    float kx[3], ky[3], kc[3];
};

// Full per-triangle setup; also emits the raster coefficient records.
__device__ __forceinline__ TriBin tri_setup(const int* __restrict__ faces,
                                            const float* __restrict__ verts,
                                            const float* __restrict__ cams,
                                            int t, int V, int F, int S, int NT) {
    TriBin r; r.ok = 0;
    int b = t / F;
    const int* fv = faces + t * 3;
    float2 v0 = project_vert(verts, cams, b, b * V + fv[0]);
    float2 v1 = project_vert(verts, cams, b, b * V + fv[1]);
    float2 v2 = project_vert(verts, cams, b, b * V + fv[2]);
    float area = (v1.x - v0.x) * (v2.y - v0.y)
               - (v1.y - v0.y) * (v2.x - v0.x);
    if (!(fabsf(area) > 1e-12f)) return r;

    float minx = fminf(v0.x, fminf(v1.x, v2.x));
    float maxx = fmaxf(v0.x, fmaxf(v1.x, v2.x));
    float miny = fminf(v0.y, fminf(v1.y, v2.y));
    float maxy = fmaxf(v0.y, fmaxf(v1.y, v2.y));
    float half = 0.5f * (float)S;
    int x0 = max(0,     (int)floorf((minx + 1.0f) * half - 0.5f) - 1);
    int x1 = min(S - 1, (int)ceilf ((maxx + 1.0f) * half - 0.5f) + 1);
    int y0 = max(0,     (int)floorf((miny + 1.0f) * half - 0.5f) - 1);
    int y1 = min(S - 1, (int)ceilf ((maxy + 1.0f) * half - 0.5f) + 1);
    if (x1 < x0 || y1 < y0) return r;

    r.ok = 1;
    r.tx0 = x0 / TS; r.ty0 = y0 / TS;
    r.tbase = b * NT * NT;
    r.sx = x1 / TS - r.tx0 + 1;
    r.ntiles = r.sx * (y1 / TS - r.ty0 + 1);

    g_triA[t] = make_float4(v1.x, v1.y, v2.y - v1.y, v2.x - v1.x);
    g_triB[t] = make_float4(v2.x, v2.y, v0.y - v2.y, v0.x - v2.x);
    g_triC[t] = make_float4(v0.x, v0.y, v1.y - v0.y, v1.x - v0.x);

    float ss = area > 0.0f ? -1.0f : 1.0f;   // interior: ss*w >= 0
    float axv[3] = {v1.x, v2.x, v0.x};
    float ayv[3] = {v1.y, v2.y, v0.y};
    float dXv[3] = {v2.x - v1.x, v0.x - v2.x, v1.x - v0.x};
    float dYv[3] = {v2.y - v1.y, v0.y - v2.y, v1.y - v0.y};
#pragma unroll
    for (int e = 0; e < 3; e++) {
        r.kx[e] = ss * dYv[e];
        r.ky[e] = -ss * dXv[e];
        r.kc[e] = ss * (ayv[e] * dXv[e] - axv[e] * dYv[e]);
    }
    return r;
}

// Corner-based tile classification on broadcast scalars: 0 cull, 1 list, 2 full.
__device__ __forceinline__ int tile_class_s(
    const float* kx, const float* ky, const float* kc,
    int tx, int ty, float invS, float span)
{
    float cx0 = (2.0f * (float)(tx * TS) + 1.0f) * invS - 1.0f;
    float cy0 = (2.0f * (float)(ty * TS) + 1.0f) * invS - 1.0f;
    const float MARGIN = 1e-4f;
    bool full = true, cull = false;
#pragma unroll
    for (int e = 0; e < 3; e++) {
        float base = kx[e] * cx0 + ky[e] * cy0 + kc[e];
        float dxs = kx[e] * span, dys = ky[e] * span;
        float tmin = base + fminf(dxs, 0.0f) + fminf(dys, 0.0f);
        float tmax = base + fmaxf(dxs, 0.0f) + fmaxf(dys, 0.0f);
        full = full && (tmin >= MARGIN);
        cull = cull || (tmax <= -MARGIN);
    }
    return full ? 2 : (cull ? 0 : 1);
}

// Warp-parallel binning, lane-parallel setup (lane l < TPW owns triangle
// base+l). Phase 1: classify/count via shfl broadcast; phase 2: bitmask replay.
__global__ void __launch_bounds__(256)
bin_kernel(const int* __restrict__ faces, const float* __restrict__ verts,
           const float* __restrict__ cams, int B, int V, int F, int S, int NT) {
    __shared__ int s_cnt[MAXTILES];
    __shared__ int s_base[MAXTILES];
    for (int i = threadIdx.x; i < MAXTILES; i += 256) s_cnt[i] = 0;
    __syncthreads();

    int BF = B * F;
    int warpId = blockIdx.x * 8 + (threadIdx.x >> 5);
    int warpBase = warpId * TPW;
    int lane = threadIdx.x & 31;
    float invS = 1.0f / (float)S;
    float span = 30.0f * invS;   // ndc span between tile corner pixel centers
    const unsigned int FULLM = 0xFFFFFFFFu;

    TriBin mine; mine.ok = 0;
    if (lane < TPW && warpBase + lane < BF)
        mine = tri_setup(faces, verts, cams, warpBase + lane, V, F, S, NT);

    unsigned int lmask[TPW];     // bit i: tile (i*32+lane) of triangle k is "list"
    unsigned int lmeta[TPW];     // packed tx0|ty0<<5|sx<<10|tbase<<15
#pragma unroll
    for (int k = 0; k < TPW; k++) { lmask[k] = 0u; lmeta[k] = 0u; }

    // phase 1: classify + count + full flags
#pragma unroll
    for (int k = 0; k < TPW; k++) {
        if (warpBase + k >= BF) break;
        if (!__shfl_sync(FULLM, mine.ok, k)) continue;
        float kx[3], ky[3], kc[3];
#pragma unroll
        for (int e = 0; e < 3; e++) {
            kx[e] = __shfl_sync(FULLM, mine.kx[e], k);
            ky[e] = __shfl_sync(FULLM, mine.ky[e], k);
            kc[e] = __shfl_sync(FULLM, mine.kc[e], k);
        }
        int tx0    = __shfl_sync(FULLM, mine.tx0, k);
        int ty0    = __shfl_sync(FULLM, mine.ty0, k);
        int sx     = __shfl_sync(FULLM, mine.sx, k);
        int ntiles = __shfl_sync(FULLM, mine.ntiles, k);
        int tbase  = __shfl_sync(FULLM, mine.tbase, k);
        lmeta[k] = (unsigned int)tx0 | ((unsigned int)ty0 << 5)
                 | ((unsigned int)sx << 10) | ((unsigned int)tbase << 15);
        unsigned int m = 0u;
        for (int i = lane; i < ntiles; i += 32) {
            int tx = tx0 + (i % sx);
            int ty = ty0 + (i / sx);
            int tile = tbase + ty * NT + tx;
            int c = tile_class_s(kx, ky, kc, tx, ty, invS, span);
            if (c == 2)      g_full[tile] = 1;
            else if (c == 1) { m |= 1u << (i >> 5); atomicAdd(&s_cnt[tile], 1); }
        }
        lmask[k] = m;
    }
    __syncthreads();
    for (int i = threadIdx.x; i < MAXTILES; i += 256) {
        int c = s_cnt[i];
        s_base[i] = c ? atomicAdd(&g_cnt[i], c) : 0;
        s_cnt[i] = 0;
    }
    __syncthreads();
    // phase 2: replay bitmasks and scatter
#pragma unroll
    for (int k = 0; k < TPW; k++) {
        unsigned int m = lmask[k];
        if (!m) continue;
        int t = warpBase + k;
        unsigned int me = lmeta[k];
        int tx0   = me & 31;
        int ty0   = (me >> 5) & 31;
        int sx    = (me >> 10) & 31;
        int tbase = me >> 15;
        while (m) {
            int bit = __ffs(m) - 1;
            m &= m - 1;
            int i = (bit << 5) + lane;
            int tx = tx0 + (i % sx);
            int ty = ty0 + (i / sx);
            int tile = tbase + ty * NT + tx;
            int pos = s_base[tile] + atomicAdd(&s_cnt[tile], 1);
            g_bins[tile * CAP + pos] = t;
        }
    }
}

// NSPLIT sub-CTAs per (batch, 16x16 tile); each scans a strided quarter of
// the tile's list (byte-identical edge test, warp/CTA early exit), ballots
// coverage into a per-tile 256-bit mask, and the LAST arriving sub-CTA
// writes the float output and resets all per-tile state for the next replay.
__global__ void __launch_bounds__(256)
raster_kernel(float* __restrict__ out, int S, int NT) {
    __shared__ float4 sA[BATCH], sB[BATCH], sC[BATCH];
    __shared__ int s_old;
    __shared__ unsigned int s_mask[8];

    int tile = blockIdx.x >> 2;
    int part = blockIdx.x & (NSPLIT - 1);
    int b   = tile / (NT * NT);
    int rem = tile - b * (NT * NT);
    int tyT = rem / NT, txT = rem - tyT * NT;
    int tid = threadIdx.x;
    int ix = txT * TS + (tid & (TS - 1));
    int iy = tyT * TS + (tid >> 4);
    float* dst = out + (b * S + iy) * S + ix;

    int n    = g_cnt[tile];
    int full = g_full[tile];

    const unsigned int FULLM = 0xFFFFFFFFu;
    bool cov = false;

    if (!full && n > 0) {
        int m = (n - part + NSPLIT - 1) / NSPLIT;   // my strided sublist length
        const int* list = g_bins + tile * CAP;
        float invS = 1.0f / (float)S;
        float px = (2.0f * (float)ix + 1.0f) * invS - 1.0f;
        float py = (2.0f * (float)iy + 1.0f) * invS - 1.0f;

        for (int k0 = 0; k0 < m; k0 += BATCH) {
            int cnt = min(BATCH, m - k0);
            if (tid < cnt) {
                int f = list[part + NSPLIT * (k0 + tid)];
                sA[tid] = g_triA[f];
            } else if (tid < 2 * cnt) {
                int f = list[part + NSPLIT * (k0 + tid - cnt)];
                sB[tid - cnt] = g_triB[f];
            } else if (tid < 3 * cnt) {
                int f = list[part + NSPLIT * (k0 + tid - 2 * cnt)];
                sC[tid - 2 * cnt] = g_triC[f];
            }
            __syncthreads();

            for (int kc = 0; kc < cnt && !__all_sync(FULLM, cov); kc += 8) {
                int ke = min(kc + 8, cnt);
                #pragma unroll 8
                for (int k = kc; k < ke; k++) {
                    float4 A  = sA[k];
                    float4 Bq = sB[k];
                    float4 C  = sC[k];
                    float w0 = (px - A.x)  * A.z  - (py - A.y)  * A.w;
                    float w1 = (px - Bq.x) * Bq.z - (py - Bq.y) * Bq.w;
                    float w2 = (px - C.x)  * C.z  - (py - C.y)  * C.w;
                    float wmin = fminf(w0, fminf(w1, w2));
                    float wmax = fmaxf(w0, fmaxf(w1, w2));
                    cov |= (wmin >= 0.0f) | (wmax <= 0.0f);
                }
            }
            if (__syncthreads_and((int)cov)) break;   // also guards smem reuse
        }
        // publish this sub-CTA's coverage bits
        unsigned int wm = __ballot_sync(FULLM, cov);
        if ((tid & 31) == 0 && wm)
            atomicOr(&g_mask[tile * 8 + (tid >> 5)], wm);
    }

    // arrival protocol: every sub-CTA arrives exactly once
    __threadfence();
    __syncthreads();                 // all atomicOrs of this CTA are issued
    if (tid == 0) s_old = atomicAdd(&g_done[tile], 1);
    __syncthreads();

    if (s_old == NSPLIT - 1) {       // last sub-CTA: combine, write, reset
        __threadfence();
        if (tid < 8) s_mask[tid] = atomicExch(&g_mask[tile * 8 + tid], 0u);
        __syncthreads();
        float val;
        if (full) val = 1.0f;
        else      val = ((s_mask[tid >> 5] >> (tid & 31)) & 1u) ? 1.0f : 0.0f;
        *dst = val;
        if (tid == 0) { g_done[tile] = 0; g_cnt[tile] = 0; g_full[tile] = 0; }
    }
}

extern "C" void kernel_launch(void* const* d_in, const int* in_sizes, int n_in,
                              void* d_out, int out_size) {
    const float* verts = (const float*)d_in[0];   // [B,V,3] fp32
    const int*   faces = (const int*)d_in[1];     // [B,F,3] int32
    const float* cams  = (const float*)d_in[2];   // [B,3]   fp32

    int B = in_sizes[2] / 3;
    int V = in_sizes[0] / (3 * B);
    int F = in_sizes[1] / (3 * B);
    int S = 256;
    {   // derive S from out_size (S*S = out_size/B, S a power of two)
        int ss = out_size / B;
        int s = 1;
        while (s * s < ss) s <<= 1;
        if (s * s == ss) S = s;
    }
    int NT = S / TS;

    float* out = (float*)d_out;

    int binCTAs = (B * F + 8 * TPW - 1) / (8 * TPW);   // 8 warps/CTA
    bin_kernel<<<binCTAs, 256>>>(faces, verts, cams, B, V, F, S, NT);
    raster_kernel<<<B * NT * NT * NSPLIT, 256>>>(out, S, NT);
}

// round 12
// speedup vs baseline: 7.6212x; 1.0089x over previous
#include <cuda_runtime.h>

// ---- static scratch (allocation-free; zero-initialized at module load) ----
#define MAX_BF    32768            // B*F faces
#define TS        16               // tile size in pixels
#define MAXTILES  1024             // B * (S/TS)^2  (2*256 = 512 used)
#define CAP       8192             // per-tile list capacity (>= F)
#define BATCH     64               // triangles staged per smem batch
#define TPW       4                // triangles per warp in binner (lane-parallel)
#define NSPLIT    4                // sub-CTAs cooperating on one tile

__device__ float4 g_triA[MAX_BF];  // (v1x, v1y, dY0, dX0)
__device__ float4 g_triB[MAX_BF];  // (v2x, v2y, dY1, dX1)
__device__ float4 g_triC[MAX_BF];  // (v0x, v0y, dY2, dX2)
__device__ int    g_cnt[MAXTILES];    // reset each run (raster)
__device__ int    g_full[MAXTILES];   // reset each run (raster)
__device__ int    g_done[MAXTILES];   // reset each run (raster)
__device__ unsigned int g_mask[MAXTILES * 8];  // 256-bit coverage per tile
__device__ int    g_bins[MAXTILES * CAP];

// Reference-identical projection of one vertex.
__device__ __forceinline__ float2 project_vert(const float* __restrict__ verts,
                                               const float* __restrict__ cams,
                                               int b, int vi) {
    float f  = cams[b * 3 + 0];
    float cx = cams[b * 3 + 1];
    float cy = cams[b * 3 + 2];
    float image_size = cams[1] * 2.0f;   // cams[0,1] * 2 per reference
    const float* p = verts + vi * 3;
    float x = p[0], y = p[1], z = p[2];
    float px = f * x / z + cx;
    float py = f * y / z + cy;
    return make_float2(px / image_size * 2.0f - 1.0f,
                       py / image_size * 2.0f - 1.0f);
}

struct TriBin {
    int   ok;
    int   tx0, ty0, tbase, sx, ntiles;
    float kx[3], ky[3], kc[3];
};

// Full per-triangle setup; also emits the raster coefficient records.
__device__ __forceinline__ TriBin tri_setup(const int* __restrict__ faces,
                                            const float* __restrict__ verts,
                                            const float* __restrict__ cams,
                                            int t, int V, int F, int S, int NT) {
    TriBin r; r.ok = 0;
    int b = t / F;
    const int* fv = faces + t * 3;
    float2 v0 = project_vert(verts, cams, b, b * V + fv[0]);
    float2 v1 = project_vert(verts, cams, b, b * V + fv[1]);
    float2 v2 = project_vert(verts, cams, b, b * V + fv[2]);
    float area = (v1.x - v0.x) * (v2.y - v0.y)
               - (v1.y - v0.y) * (v2.x - v0.x);
    if (!(fabsf(area) > 1e-12f)) return r;

    float minx = fminf(v0.x, fminf(v1.x, v2.x));
    float maxx = fmaxf(v0.x, fmaxf(v1.x, v2.x));
    float miny = fminf(v0.y, fminf(v1.y, v2.y));
    float maxy = fmaxf(v0.y, fmaxf(v1.y, v2.y));
    float half = 0.5f * (float)S;
    int x0 = max(0,     (int)floorf((minx + 1.0f) * half - 0.5f) - 1);
    int x1 = min(S - 1, (int)ceilf ((maxx + 1.0f) * half - 0.5f) + 1);
    int y0 = max(0,     (int)floorf((miny + 1.0f) * half - 0.5f) - 1);
    int y1 = min(S - 1, (int)ceilf ((maxy + 1.0f) * half - 0.5f) + 1);
    if (x1 < x0 || y1 < y0) return r;

    r.ok = 1;
    r.tx0 = x0 / TS; r.ty0 = y0 / TS;
    r.tbase = b * NT * NT;
    r.sx = x1 / TS - r.tx0 + 1;
    r.ntiles = r.sx * (y1 / TS - r.ty0 + 1);

    g_triA[t] = make_float4(v1.x, v1.y, v2.y - v1.y, v2.x - v1.x);
    g_triB[t] = make_float4(v2.x, v2.y, v0.y - v2.y, v0.x - v2.x);
    g_triC[t] = make_float4(v0.x, v0.y, v1.y - v0.y, v1.x - v0.x);

    float ss = area > 0.0f ? -1.0f : 1.0f;   // interior: ss*w >= 0
    float axv[3] = {v1.x, v2.x, v0.x};
    float ayv[3] = {v1.y, v2.y, v0.y};
    float dXv[3] = {v2.x - v1.x, v0.x - v2.x, v1.x - v0.x};
    float dYv[3] = {v2.y - v1.y, v0.y - v2.y, v1.y - v0.y};
#pragma unroll
    for (int e = 0; e < 3; e++) {
        r.kx[e] = ss * dYv[e];
        r.ky[e] = -ss * dXv[e];
        r.kc[e] = ss * (ayv[e] * dXv[e] - axv[e] * dYv[e]);
    }
    return r;
}

// Corner-based tile classification on broadcast scalars: 0 cull, 1 list, 2 full.
__device__ __forceinline__ int tile_class_s(
    const float* kx, const float* ky, const float* kc,
    int tx, int ty, float invS, float span)
{
    float cx0 = (2.0f * (float)(tx * TS) + 1.0f) * invS - 1.0f;
    float cy0 = (2.0f * (float)(ty * TS) + 1.0f) * invS - 1.0f;
    const float MARGIN = 1e-4f;
    bool full = true, cull = false;
#pragma unroll
    for (int e = 0; e < 3; e++) {
        float base = kx[e] * cx0 + ky[e] * cy0 + kc[e];
        float dxs = kx[e] * span, dys = ky[e] * span;
        float tmin = base + fminf(dxs, 0.0f) + fminf(dys, 0.0f);
        float tmax = base + fmaxf(dxs, 0.0f) + fmaxf(dys, 0.0f);
        full = full && (tmin >= MARGIN);
        cull = cull || (tmax <= -MARGIN);
    }
    return full ? 2 : (cull ? 0 : 1);
}

// Warp-parallel binning, lane-parallel setup (lane l < TPW owns triangle
// base+l). Phase 1: classify/count via shfl broadcast; phase 2: bitmask replay.
__global__ void __launch_bounds__(256)
bin_kernel(const int* __restrict__ faces, const float* __restrict__ verts,
           const float* __restrict__ cams, int B, int V, int F, int S, int NT) {
    __shared__ int s_cnt[MAXTILES];
    __shared__ int s_base[MAXTILES];
    for (int i = threadIdx.x; i < MAXTILES; i += 256) s_cnt[i] = 0;
    __syncthreads();

    int BF = B * F;
    int warpId = blockIdx.x * 8 + (threadIdx.x >> 5);
    int warpBase = warpId * TPW;
    int lane = threadIdx.x & 31;
    float invS = 1.0f / (float)S;
    float span = 30.0f * invS;   // ndc span between tile corner pixel centers
    const unsigned int FULLM = 0xFFFFFFFFu;

    TriBin mine; mine.ok = 0;
    if (lane < TPW && warpBase + lane < BF)
        mine = tri_setup(faces, verts, cams, warpBase + lane, V, F, S, NT);

    unsigned int lmask[TPW];     // bit i: tile (i*32+lane) of triangle k is "list"
    unsigned int lmeta[TPW];     // packed tx0|ty0<<5|sx<<10|tbase<<15
#pragma unroll
    for (int k = 0; k < TPW; k++) { lmask[k] = 0u; lmeta[k] = 0u; }

    // phase 1: classify + count + full flags
#pragma unroll
    for (int k = 0; k < TPW; k++) {
        if (warpBase + k >= BF) break;
        if (!__shfl_sync(FULLM, mine.ok, k)) continue;
        float kx[3], ky[3], kc[3];
#pragma unroll
        for (int e = 0; e < 3; e++) {
            kx[e] = __shfl_sync(FULLM, mine.kx[e], k);
            ky[e] = __shfl_sync(FULLM, mine.ky[e], k);
            kc[e] = __shfl_sync(FULLM, mine.kc[e], k);
        }
        int tx0    = __shfl_sync(FULLM, mine.tx0, k);
        int ty0    = __shfl_sync(FULLM, mine.ty0, k);
        int sx     = __shfl_sync(FULLM, mine.sx, k);
        int ntiles = __shfl_sync(FULLM, mine.ntiles, k);
        int tbase  = __shfl_sync(FULLM, mine.tbase, k);
        lmeta[k] = (unsigned int)tx0 | ((unsigned int)ty0 << 5)
                 | ((unsigned int)sx << 10) | ((unsigned int)tbase << 15);
        unsigned int m = 0u;
        for (int i = lane; i < ntiles; i += 32) {
            int tx = tx0 + (i % sx);
            int ty = ty0 + (i / sx);
            int tile = tbase + ty * NT + tx;
            int c = tile_class_s(kx, ky, kc, tx, ty, invS, span);
            if (c == 2)      g_full[tile] = 1;
            else if (c == 1) { m |= 1u << (i >> 5); atomicAdd(&s_cnt[tile], 1); }
        }
        lmask[k] = m;
    }
    __syncthreads();
    for (int i = threadIdx.x; i < MAXTILES; i += 256) {
        int c = s_cnt[i];
        s_base[i] = c ? atomicAdd(&g_cnt[i], c) : 0;
        s_cnt[i] = 0;
    }
    __syncthreads();
    // phase 2: replay bitmasks and scatter
#pragma unroll
    for (int k = 0; k < TPW; k++) {
        unsigned int m = lmask[k];
        if (!m) continue;
        int t = warpBase + k;
        unsigned int me = lmeta[k];
        int tx0   = me & 31;
        int ty0   = (me >> 5) & 31;
        int sx    = (me >> 10) & 31;
        int tbase = me >> 15;
        while (m) {
            int bit = __ffs(m) - 1;
            m &= m - 1;
            int i = (bit << 5) + lane;
            int tx = tx0 + (i % sx);
            int ty = ty0 + (i / sx);
            int tile = tbase + ty * NT + tx;
            int pos = s_base[tile] + atomicAdd(&s_cnt[tile], 1);
            g_bins[tile * CAP + pos] = t;
        }
    }
}

// NSPLIT sub-CTAs per tile, scanning strided sublists. After each batch the
// sub-CTAs SHARE coverage through the per-tile mask (atomicOr publish +
// __ldcg read-back; bits are monotonic so staleness is benign) — covered
// pixels stop scanning as soon as ANY sub-CTA covers them. Last arriving
// sub-CTA combines, writes floats, and resets state for the next replay.
__global__ void __launch_bounds__(256)
raster_kernel(float* __restrict__ out, int S, int NT) {
    __shared__ float4 sA[BATCH], sB[BATCH], sC[BATCH];
    __shared__ int s_old;
    __shared__ unsigned int s_mask[8];

    int tile = blockIdx.x >> 2;
    int part = blockIdx.x & (NSPLIT - 1);
    int b   = tile / (NT * NT);
    int rem = tile - b * (NT * NT);
    int tyT = rem / NT, txT = rem - tyT * NT;
    int tid = threadIdx.x;
    int ix = txT * TS + (tid & (TS - 1));
    int iy = tyT * TS + (tid >> 4);
    float* dst = out + (b * S + iy) * S + ix;

    int n    = g_cnt[tile];
    int full = g_full[tile];

    const unsigned int FULLM = 0xFFFFFFFFu;
    unsigned int* mword = &g_mask[tile * 8 + (tid >> 5)];
    unsigned int mybit = 1u << (tid & 31);
    bool cov = false;

    if (!full && n > 0) {
        int m = (n - part + NSPLIT - 1) / NSPLIT;   // my strided sublist length
        const int* list = g_bins + tile * CAP;
        float invS = 1.0f / (float)S;
        float px = (2.0f * (float)ix + 1.0f) * invS - 1.0f;
        float py = (2.0f * (float)iy + 1.0f) * invS - 1.0f;

        for (int k0 = 0; k0 < m; k0 += BATCH) {
            int cnt = min(BATCH, m - k0);
            if (tid < cnt) {
                int f = list[part + NSPLIT * (k0 + tid)];
                sA[tid] = g_triA[f];
            } else if (tid < 2 * cnt) {
                int f = list[part + NSPLIT * (k0 + tid - cnt)];
                sB[tid - cnt] = g_triB[f];
            } else if (tid < 3 * cnt) {
                int f = list[part + NSPLIT * (k0 + tid - 2 * cnt)];
                sC[tid - 2 * cnt] = g_triC[f];
            }
            __syncthreads();

            for (int kc = 0; kc < cnt && !__all_sync(FULLM, cov); kc += 8) {
                int ke = min(kc + 8, cnt);
                #pragma unroll 8
                for (int k = kc; k < ke; k++) {
                    float4 A  = sA[k];
                    float4 Bq = sB[k];
                    float4 C  = sC[k];
                    float w0 = (px - A.x)  * A.z  - (py - A.y)  * A.w;
                    float w1 = (px - Bq.x) * Bq.z - (py - Bq.y) * Bq.w;
                    float w2 = (px - C.x)  * C.z  - (py - C.y)  * C.w;
                    float wmin = fminf(w0, fminf(w1, w2));
                    float wmax = fmaxf(w0, fmaxf(w1, w2));
                    cov |= (wmin >= 0.0f) | (wmax <= 0.0f);
                }
            }
            // publish my warp's coverage, then import peers' progress
            unsigned int wm = __ballot_sync(FULLM, cov);
            if ((tid & 31) == 0 && wm) atomicOr(mword, wm);
            cov |= (__ldcg(mword) & mybit) != 0u;
            if (__syncthreads_and((int)cov)) break;   // also guards smem reuse
        }
        // final publish (covers break path and last batch)
        unsigned int wm = __ballot_sync(FULLM, cov);
        if ((tid & 31) == 0 && wm) atomicOr(mword, wm);
    }

    // arrival protocol: every sub-CTA arrives exactly once
    __threadfence();
    __syncthreads();                 // all atomicOrs of this CTA are issued
    if (tid == 0) s_old = atomicAdd(&g_done[tile], 1);
    __syncthreads();

    if (s_old == NSPLIT - 1) {       // last sub-CTA: combine, write, reset
        __threadfence();
        if (tid < 8) s_mask[tid] = atomicExch(&g_mask[tile * 8 + tid], 0u);
        __syncthreads();
        float val;
        if (full) val = 1.0f;
        else      val = ((s_mask[tid >> 5] >> (tid & 31)) & 1u) ? 1.0f : 0.0f;
        *dst = val;
        if (tid == 0) { g_done[tile] = 0; g_cnt[tile] = 0; g_full[tile] = 0; }
    }
}

extern "C" void kernel_launch(void* const* d_in, const int* in_sizes, int n_in,
                              void* d_out, int out_size) {
    const float* verts = (const float*)d_in[0];   // [B,V,3] fp32
    const int*   faces = (const int*)d_in[1];     // [B,F,3] int32
    const float* cams  = (const float*)d_in[2];   // [B,3]   fp32

    int B = in_sizes[2] / 3;
    int V = in_sizes[0] / (3 * B);
    int F = in_sizes[1] / (3 * B);
    int S = 256;
    {   // derive S from out_size (S*S = out_size/B, S a power of two)
        int ss = out_size / B;
        int s = 1;
        while (s * s < ss) s <<= 1;
        if (s * s == ss) S = s;
    }
    int NT = S / TS;

    float* out = (float*)d_out;

    int binCTAs = (B * F + 8 * TPW - 1) / (8 * TPW);   // 8 warps/CTA
    bin_kernel<<<binCTAs, 256>>>(faces, verts, cams, B, V, F, S, NT);
    raster_kernel<<<B * NT * NT * NSPLIT, 256>>>(out, S, NT);
}